// round 12
// baseline (speedup 1.0000x reference)
#include <cuda_runtime.h>
#include <cuda_bf16.h>
#include <cuda_fp16.h>
#include <cstdint>

// Problem constants
#define BB 2
#define SS 2048
#define DD 1024
#define HH 16
#define HD 64
#define BH (BB*HH)          // 32
#define MROWS (BB*SS)       // 4096
#define E3D (3*DD)          // 3072

// Scratch (device globals; allocation-free kernel_launch)
__device__ float g_V[(size_t)BH * SS * HD];            // 16 MB
__device__ float g_L[(size_t)BH * SS * SS];            // 512 MB (log2-domain logits)
__device__ float2 g_part[(size_t)BH * SS * 32];        // per (row, ntile) {m_loc, z_loc}
__device__ float4 g_stats[(size_t)BH * SS];            // {m2, cut2, 0, u}
__device__ __half g_Xh[(size_t)MROWS * DD];            // x 3-term split
__device__ __half g_Xm[(size_t)MROWS * DD];
__device__ __half g_Xl[(size_t)MROWS * DD];
__device__ __half g_Wh[(size_t)E3D * DD];              // qkv_w 3-term split
__device__ __half g_Wm[(size_t)E3D * DD];
__device__ __half g_Wl[(size_t)E3D * DD];
__device__ __half g_Qh[(size_t)BH * SS * HD];          // Q 3-term [bh][s][hd]
__device__ __half g_Qm[(size_t)BH * SS * HD];
__device__ __half g_Ql[(size_t)BH * SS * HD];
__device__ __half g_Kh[(size_t)BH * SS * HD];          // K 3-term
__device__ __half g_Km[(size_t)BH * SS * HD];
__device__ __half g_Kl[(size_t)BH * SS * HD];
__device__ __nv_bfloat16 g_Vhi[(size_t)BH * HD * SS];  // V^T hi [bh][hd][s]
__device__ __nv_bfloat16 g_Vlo[(size_t)BH * HD * SS];  // V^T lo
__device__ __nv_bfloat16 g_valsH[(size_t)MROWS * DD];  // attn out hi [m][d]
__device__ __nv_bfloat16 g_valsL[(size_t)MROWS * DD];  // attn out lo
__device__ __nv_bfloat16 g_OWh[(size_t)DD * DD];       // o_w hi [n][k]
__device__ __nv_bfloat16 g_OWl[(size_t)DD * DD];       // o_w lo

#define C_G1 2.44140625e-4f            // 2^-12
#define C_G2 5.9604644775390625e-8f    // 2^-24
#define LOG2E 1.44269504088896340736f

// ===========================================================================
// Helpers
// ===========================================================================
__device__ __forceinline__ uint32_t smem_u32(const void* p) {
    uint32_t a;
    asm("{ .reg .u64 t; cvta.to.shared.u64 t, %1; cvt.u32.u64 %0, t; }" : "=r"(a) : "l"(p));
    return a;
}
__device__ __forceinline__ uint32_t pack16(uint16_t a, uint16_t b) {
    return (uint32_t)a | ((uint32_t)b << 16);
}
__device__ __forceinline__ float ex2(float x) {
    float r; asm("ex2.approx.f32 %0, %1;" : "=f"(r) : "f"(x)); return r;
}
__device__ __forceinline__ void split_bf(float x, uint16_t& h, uint16_t& l) {
    __nv_bfloat16 hb = __float2bfloat16(x);
    float r = x - __bfloat162float(hb);
    __nv_bfloat16 lb = __float2bfloat16(r);
    h = *reinterpret_cast<uint16_t*>(&hb);
    l = *reinterpret_cast<uint16_t*>(&lb);
}
// scaled 3-term fp16 split: x = h + m*2^-12 + l*2^-24 (+O(x*2^-35))
__device__ __forceinline__ void split3(float x, uint16_t& h, uint16_t& m, uint16_t& l) {
    __half a = __float2half_rn(x);
    float r1 = x - __half2float(a);
    __half b = __float2half_rn(r1 * 4096.0f);
    float r2 = r1 - __half2float(b) * C_G1;
    __half c = __float2half_rn(r2 * 16777216.0f);
    h = *reinterpret_cast<uint16_t*>(&a);
    m = *reinterpret_cast<uint16_t*>(&b);
    l = *reinterpret_cast<uint16_t*>(&c);
}
__device__ __forceinline__ void ldsm4(uint32_t* r, uint32_t addr) {
    asm volatile("ldmatrix.sync.aligned.m8n8.x4.shared.b16 {%0,%1,%2,%3}, [%4];"
                 : "=r"(r[0]), "=r"(r[1]), "=r"(r[2]), "=r"(r[3]) : "r"(addr));
}
__device__ __forceinline__ void mma16816(float* c, const uint32_t* a,
                                         uint32_t b0, uint32_t b1) {
    asm volatile(
        "mma.sync.aligned.m16n8k16.row.col.f32.bf16.bf16.f32 "
        "{%0,%1,%2,%3}, {%4,%5,%6,%7}, {%8,%9}, {%0,%1,%2,%3};"
        : "+f"(c[0]), "+f"(c[1]), "+f"(c[2]), "+f"(c[3])
        : "r"(a[0]), "r"(a[1]), "r"(a[2]), "r"(a[3]), "r"(b0), "r"(b1));
}
__device__ __forceinline__ void mma16816h(float* c, const uint32_t* a,
                                          uint32_t b0, uint32_t b1) {
    asm volatile(
        "mma.sync.aligned.m16n8k16.row.col.f32.f16.f16.f32 "
        "{%0,%1,%2,%3}, {%4,%5,%6,%7}, {%8,%9}, {%0,%1,%2,%3};"
        : "+f"(c[0]), "+f"(c[1]), "+f"(c[2]), "+f"(c[3])
        : "r"(a[0]), "r"(a[1]), "r"(a[2]), "r"(a[3]), "r"(b0), "r"(b1));
}
__device__ __forceinline__ void cp16(uint32_t dst, const void* src) {
    asm volatile("cp.async.cg.shared.global [%0], [%1], 16;" :: "r"(dst), "l"(src));
}
#define CP_COMMIT() asm volatile("cp.async.commit_group;")
#define CP_WAIT1()  asm volatile("cp.async.wait_group 1;")
#define CP_WAIT0()  asm volatile("cp.async.wait_group 0;")

#define TSTRIDE 40   // 16-bit elems per smem row for chunked tiles (80B)
#define LSTRIDE 72   // 16-bit elems per smem row for full-K logits tiles (144B)

// ===========================================================================
// Kernel 0: fp32 -> scaled 3-term fp16 split. 4 elems/thread.
// ===========================================================================
__global__ __launch_bounds__(256) void split3_kernel(
    const float* __restrict__ src, __half* __restrict__ dh,
    __half* __restrict__ dm, __half* __restrict__ dl)
{
    const int i = blockIdx.x * 256 + threadIdx.x;
    float4 v = ((const float4*)src)[i];
    uint16_t h[4], m[4], l[4];
    split3(v.x, h[0], m[0], l[0]); split3(v.y, h[1], m[1], l[1]);
    split3(v.z, h[2], m[2], l[2]); split3(v.w, h[3], m[3], l[3]);
    ((uint2*)dh)[i] = make_uint2(pack16(h[0],h[1]), pack16(h[2],h[3]));
    ((uint2*)dm)[i] = make_uint2(pack16(m[0],m[1]), pack16(m[2],m[3]));
    ((uint2*)dl)[i] = make_uint2(pack16(l[0],l[1]), pack16(l[2],l[3]));
}

// ===========================================================================
// Kernel 1: QKV projection via 3-term fp16 HMMA — 128-thread CTAs, M=64 tile.
// ===========================================================================
#define QKV_BUF 30720   // A 3*5120 | B 3*5120
#define QKV_SMEM (2*QKV_BUF)
__global__ __launch_bounds__(128) void qkv_mma_kernel(const float* __restrict__ bias)
{
    extern __shared__ __align__(16) char qsm[];
    const int tid = threadIdx.x;
    const int lane = tid & 31, wid = tid >> 5;
    const int wm = wid & 1, wn = wid >> 1;
    const int m0 = blockIdx.x * 64;
    const int e0 = blockIdx.y * 64;
    const int typ = (e0 >> 6) % 3;          // 0=Q, 1=K, 2=V
    const bool vmode = (typ == 2);
    const int head = e0 / 192;

    const uint32_t sb0 = smem_u32(qsm);
    const int rA = tid >> 1;                 // 0..63
    const int gA = (tid & 1) * 2;            // 16B-group base

    const __half* XA[3] = { g_Xh, g_Xm, g_Xl };
    const __half* WB[3] = { g_Wh, g_Wm, g_Wl };
    const uint32_t Aoff[3] = { 0u, 5120u, 10240u };
    const uint32_t Boff[3] = { 15360u, 20480u, 25600u };
    const int nTiles = vmode ? 2 : 3;

    const int a_row = wm * 32 + ((lane >> 3) & 1) * 8 + (lane & 7);
    const int a_kadd = ((lane >> 4) & 1) * 8;
    const int b_row = wn * 32 + ((lane >> 4) & 1) * 8 + (lane & 7);
    const int b_kadd = ((lane >> 3) & 1) * 8;

    float acc0[2][4][4], acc1[2][4][4], acc2[2][4][4], gr0[2][4][4];
    #pragma unroll
    for (int i = 0; i < 2; i++)
        #pragma unroll
        for (int j = 0; j < 4; j++)
            #pragma unroll
            for (int r = 0; r < 4; r++) {
                acc0[i][j][r]=0.f; acc1[i][j][r]=0.f; acc2[i][j][r]=0.f; gr0[i][j][r]=0.f;
            }

    auto issue = [&](int c, int bb) {
        const uint32_t sb = sb0 + bb * QKV_BUF;
        #pragma unroll
        for (int T = 0; T < 3; ++T) {
            if (T >= nTiles) break;
            const __half* srcA = XA[T] + (size_t)(m0 + rA) * DD + c * 32 + gA * 8;
            uint32_t dstA = sb + Aoff[T] + (uint32_t)(rA * TSTRIDE + gA * 8) * 2;
            cp16(dstA, srcA);
            cp16(dstA + 16, srcA + 8);
            const __half* srcB = WB[T] + (size_t)(e0 + rA) * DD + c * 32 + gA * 8;
            uint32_t dstB = sb + Boff[T] + (uint32_t)(rA * TSTRIDE + gA * 8) * 2;
            cp16(dstB, srcB);
            cp16(dstB + 16, srcB + 8);
        }
        CP_COMMIT();
    };

    issue(0, 0);
    const int NCH = DD / 32;   // 32
    for (int c = 0; c < NCH; ++c) {
        if (c + 1 < NCH) { issue(c + 1, (c + 1) & 1); CP_WAIT1(); }
        else             { CP_WAIT0(); }
        __syncthreads();

        const uint32_t sb = sb0 + (c & 1) * QKV_BUF;
        #pragma unroll
        for (int ks = 0; ks < 2; ++ks) {
            const int kc = ks * 16;
            uint32_t fah[2][4], fam[2][4], fal[2][4];
            uint32_t fbh[2][4], fbm[2][4], fbl[2][4];
            #pragma unroll
            for (int i = 0; i < 2; ++i) {
                uint32_t ro = (uint32_t)((a_row + i * 16) * TSTRIDE + kc + a_kadd) * 2;
                ldsm4(fah[i], sb + Aoff[0] + ro);
                ldsm4(fam[i], sb + Aoff[1] + ro);
                if (!vmode) ldsm4(fal[i], sb + Aoff[2] + ro);
            }
            #pragma unroll
            for (int p = 0; p < 2; ++p) {
                uint32_t ro = (uint32_t)((b_row + p * 16) * TSTRIDE + kc + b_kadd) * 2;
                ldsm4(fbh[p], sb + Boff[0] + ro);
                ldsm4(fbm[p], sb + Boff[1] + ro);
                if (!vmode) ldsm4(fbl[p], sb + Boff[2] + ro);
            }
            #pragma unroll
            for (int i = 0; i < 2; ++i)
                #pragma unroll
                for (int jn = 0; jn < 4; ++jn) {
                    const int p = jn >> 1, q = (jn & 1) * 2;
                    mma16816h(acc0[i][jn], fah[i], fbh[p][q], fbh[p][q + 1]);
                    mma16816h(acc1[i][jn], fah[i], fbm[p][q], fbm[p][q + 1]);
                    mma16816h(acc1[i][jn], fam[i], fbh[p][q], fbh[p][q + 1]);
                    if (!vmode) {
                        mma16816h(acc2[i][jn], fah[i], fbl[p][q], fbl[p][q + 1]);
                        mma16816h(acc2[i][jn], fam[i], fbm[p][q], fbm[p][q + 1]);
                        mma16816h(acc2[i][jn], fal[i], fbh[p][q], fbh[p][q + 1]);
                    }
                }
        }
        // drain G0 (RZ chain length 2) into RN grand accumulator
        #pragma unroll
        for (int i = 0; i < 2; ++i)
            #pragma unroll
            for (int jn = 0; jn < 4; ++jn)
                #pragma unroll
                for (int r = 0; r < 4; ++r) {
                    gr0[i][jn][r] += acc0[i][jn][r];
                    acc0[i][jn][r] = 0.f;
                }
        __syncthreads();
    }

    // epilogue
    const int g = lane >> 2, t = lane & 3;
    #pragma unroll
    for (int i = 0; i < 2; ++i) {
        #pragma unroll
        for (int jn = 0; jn < 4; ++jn) {
            const int nn = wn * 32 + jn * 8 + 2 * t;     // hd (even)
            const int e = e0 + nn;
            const float be0 = bias[e], be1 = bias[e + 1];
            #pragma unroll
            for (int half = 0; half < 2; ++half) {
                const int m = m0 + wm * 32 + i * 16 + g + half * 8;
                const int r0 = half * 2, r1 = half * 2 + 1;
                const float x0 = gr0[i][jn][r0] + C_G1 * acc1[i][jn][r0] + C_G2 * acc2[i][jn][r0] + be0;
                const float x1 = gr0[i][jn][r1] + C_G1 * acc1[i][jn][r1] + C_G2 * acc2[i][jn][r1] + be1;
                const int b = m >> 11, s = m & (SS - 1);
                const size_t base = (((size_t)(b * HH + head) * SS) + s) * HD + nn;
                if (typ == 0) {
                    uint16_t h0,m0_,l0,h1,m1,l1;
                    split3(x0, h0, m0_, l0); split3(x1, h1, m1, l1);
                    *(uint32_t*)(g_Qh + base) = pack16(h0, h1);
                    *(uint32_t*)(g_Qm + base) = pack16(m0_, m1);
                    *(uint32_t*)(g_Ql + base) = pack16(l0, l1);
                } else if (typ == 1) {
                    uint16_t h0,m0_,l0,h1,m1,l1;
                    split3(x0, h0, m0_, l0); split3(x1, h1, m1, l1);
                    *(uint32_t*)(g_Kh + base) = pack16(h0, h1);
                    *(uint32_t*)(g_Km + base) = pack16(m0_, m1);
                    *(uint32_t*)(g_Kl + base) = pack16(l0, l1);
                } else {
                    *(float2*)(g_V + base) = make_float2(x0, x1);
                }
            }
        }
    }
}

// ===========================================================================
// Kernel 2: logits via 3-term fp16 HMMA — 128-thread CTAs, M=64(q) x N=64.
// ===========================================================================
#define LG_SMEM 55296
__global__ __launch_bounds__(128) void logits_mma_kernel()
{
    extern __shared__ __align__(16) char lsm[];
    const int tid = threadIdx.x;
    const int lane = tid & 31, wid = tid >> 5;
    const int wm = wid & 1, wn = wid >> 1;
    const int bh = blockIdx.z;
    const int q0 = blockIdx.x * 64;
    const int n0 = blockIdx.y * 64;

    const uint32_t sb = smem_u32(lsm);
    const uint32_t Aoff[3] = { 0u, 9216u, 18432u };
    const uint32_t Boff[3] = { 27648u, 36864u, 46080u };
    const __half* QA[3] = { g_Qh, g_Qm, g_Ql };
    const __half* KB[3] = { g_Kh, g_Km, g_Kl };

    #pragma unroll
    for (int it = 0; it < 4; ++it) {
        const int idx = tid + it * 128;          // 0..511
        const int r = idx >> 3, gg = idx & 7;
        #pragma unroll
        for (int T = 0; T < 3; ++T) {
            cp16(sb + Aoff[T] + (uint32_t)(r * LSTRIDE + gg * 8) * 2,
                 QA[T] + ((size_t)bh * SS + q0 + r) * HD + gg * 8);
            cp16(sb + Boff[T] + (uint32_t)(r * LSTRIDE + gg * 8) * 2,
                 KB[T] + ((size_t)bh * SS + n0 + r) * HD + gg * 8);
        }
    }
    CP_COMMIT();
    CP_WAIT0();
    __syncthreads();

    const int a_row = wm * 32 + ((lane >> 3) & 1) * 8 + (lane & 7);
    const int a_kadd = ((lane >> 4) & 1) * 8;
    const int b_row = wn * 32 + ((lane >> 4) & 1) * 8 + (lane & 7);
    const int b_kadd = ((lane >> 3) & 1) * 8;

    float acc0[2][4][4], acc1[2][4][4], acc2[2][4][4], gr0[2][4][4];
    #pragma unroll
    for (int i = 0; i < 2; i++)
        #pragma unroll
        for (int j = 0; j < 4; j++)
            #pragma unroll
            for (int r = 0; r < 4; r++) {
                acc0[i][j][r]=0.f; acc1[i][j][r]=0.f; acc2[i][j][r]=0.f; gr0[i][j][r]=0.f;
            }

    #pragma unroll
    for (int ks = 0; ks < 4; ++ks) {
        const int kc = ks * 16;
        uint32_t fah[2][4], fam[2][4], fal[2][4];
        uint32_t fbh[2][4], fbm[2][4], fbl[2][4];
        #pragma unroll
        for (int i = 0; i < 2; ++i) {
            uint32_t ro = (uint32_t)((a_row + i * 16) * LSTRIDE + kc + a_kadd) * 2;
            ldsm4(fah[i], sb + Aoff[0] + ro);
            ldsm4(fam[i], sb + Aoff[1] + ro);
            ldsm4(fal[i], sb + Aoff[2] + ro);
        }
        #pragma unroll
        for (int p = 0; p < 2; ++p) {
            uint32_t ro = (uint32_t)((b_row + p * 16) * LSTRIDE + kc + b_kadd) * 2;
            ldsm4(fbh[p], sb + Boff[0] + ro);
            ldsm4(fbm[p], sb + Boff[1] + ro);
            ldsm4(fbl[p], sb + Boff[2] + ro);
        }
        #pragma unroll
        for (int i = 0; i < 2; ++i)
            #pragma unroll
            for (int jn = 0; jn < 4; ++jn) {
                const int p = jn >> 1, q = (jn & 1) * 2;
                mma16816h(acc0[i][jn], fah[i], fbh[p][q], fbh[p][q + 1]);
                mma16816h(acc1[i][jn], fah[i], fbm[p][q], fbm[p][q + 1]);
                mma16816h(acc1[i][jn], fam[i], fbh[p][q], fbh[p][q + 1]);
                mma16816h(acc2[i][jn], fah[i], fbl[p][q], fbl[p][q + 1]);
                mma16816h(acc2[i][jn], fam[i], fbm[p][q], fbm[p][q + 1]);
                mma16816h(acc2[i][jn], fal[i], fbh[p][q], fbh[p][q + 1]);
            }
        // drain G0 every kstep (RZ chain length 1)
        #pragma unroll
        for (int i = 0; i < 2; ++i)
            #pragma unroll
            for (int jn = 0; jn < 4; ++jn)
                #pragma unroll
                for (int r = 0; r < 4; ++r) {
                    gr0[i][jn][r] += acc0[i][jn][r];
                    acc0[i][jn][r] = 0.f;
                }
    }

    // epilogue: store L (log2 domain) + per-row-tile partial stats
    __syncthreads();                       // tiles dead; reuse lsm for partials
    float2* s_part = (float2*)lsm;         // [64][8]
    float* Lb = g_L + (size_t)bh * SS * SS;
    const float scl = 0.125f * LOG2E;
    const int g = lane >> 2, t = lane & 3;
    #pragma unroll
    for (int i = 0; i < 2; ++i) {
        #pragma unroll
        for (int half = 0; half < 2; ++half) {
            const int rl = wm * 32 + i * 16 + g + half * 8;
            const int q = q0 + rl;
            const int r0 = half * 2, r1 = half * 2 + 1;
            float lv[8];
            #pragma unroll
            for (int jn = 0; jn < 4; ++jn) {
                const int n = n0 + wn * 32 + jn * 8 + 2 * t;
                float2 v;
                v.x = (gr0[i][jn][r0] + C_G1 * acc1[i][jn][r0] + C_G2 * acc2[i][jn][r0]) * scl;
                v.y = (gr0[i][jn][r1] + C_G1 * acc1[i][jn][r1] + C_G2 * acc2[i][jn][r1]) * scl;
                *(float2*)(Lb + (size_t)q * SS + n) = v;
                lv[jn * 2] = v.x; lv[jn * 2 + 1] = v.y;
            }
            float mloc = lv[0];
            #pragma unroll
            for (int j = 1; j < 8; ++j) mloc = fmaxf(mloc, lv[j]);
            float zloc = 0.f;
            #pragma unroll
            for (int j = 0; j < 8; ++j) zloc += ex2(lv[j] - mloc);
            s_part[rl * 8 + wn * 4 + t] = make_float2(mloc, zloc);
        }
    }
    __syncthreads();
    if (tid < 64) {
        float2 pp[8];
        float m = -3.4e38f;
        #pragma unroll
        for (int j = 0; j < 8; ++j) {
            pp[j] = s_part[tid * 8 + j];
            m = fmaxf(m, pp[j].x);
        }
        float z = 0.f;
        #pragma unroll
        for (int j = 0; j < 8; ++j) z += pp[j].y * ex2(pp[j].x - m);
        g_part[((size_t)bh * SS + q0 + tid) * 32 + (n0 >> 6)] = make_float2(m, z);
    }
}

// ===========================================================================
// Kernel 3: combine partials -> {m2, cut2, 0, u}. One warp per row.
// ===========================================================================
__global__ __launch_bounds__(256) void combine_kernel(const float* __restrict__ thrs)
{
    const int row = blockIdx.x * 8 + (threadIdx.x >> 5);
    const int lane = threadIdx.x & 31;
    float2 p = g_part[(size_t)row * 32 + lane];
    float m = p.x;
    #pragma unroll
    for (int o = 16; o > 0; o >>= 1) m = fmaxf(m, __shfl_xor_sync(0xffffffffu, m, o));
    float z = p.y * ex2(p.x - m);
    #pragma unroll
    for (int o = 16; o > 0; o >>= 1) z += __shfl_xor_sync(0xffffffffu, z, o);
    if (lane == 0) {
        const int h = (row >> 11) & (HH - 1);
        const float tz = thrs[h] * z;
        float4 st;
        if (tz >= 1.0f) {
            st.x = 0.f; st.y = __int_as_float(0x7f800000);   // +inf
            st.z = 0.f; st.w = 1.0f;                          // uniform: w=1 everywhere
        } else {
            st.x = m; st.y = m + log2f(tz); st.z = 0.f; st.w = 0.f;
        }
        g_stats[row] = st;
    }
}

// ===========================================================================
// Kernel 3b: V transpose + bf16 hi/lo split: g_Vhi/g_Vlo [bh][hd][s]
// ===========================================================================
__global__ __launch_bounds__(256) void vsplit_kernel()
{
    __shared__ float t[64][132];
    const int bh = blockIdx.y, s0 = blockIdx.x * 128;
    const float* Vb = g_V + (size_t)bh * SS * HD;
    const int sl = threadIdx.x >> 1;
    const int hh = (threadIdx.x & 1) * 32;
    #pragma unroll
    for (int j = 0; j < 8; ++j) {
        float4 v = *(const float4*)(Vb + (size_t)(s0 + sl) * HD + hh + j * 4);
        t[hh + j*4 + 0][sl] = v.x; t[hh + j*4 + 1][sl] = v.y;
        t[hh + j*4 + 2][sl] = v.z; t[hh + j*4 + 3][sl] = v.w;
    }
    __syncthreads();
    const int row = threadIdx.x >> 2;
    const int q = (threadIdx.x & 3) * 32;
    const size_t base = ((size_t)bh * HD + row) * SS + s0 + q;
    #pragma unroll
    for (int g = 0; g < 4; ++g) {
        const float* src = &t[row][q + g * 8];
        uint16_t h[8], l[8];
        #pragma unroll
        for (int j = 0; j < 8; ++j) split_bf(src[j], h[j], l[j]);
        uint4 oh, ol;
        oh.x = pack16(h[0],h[1]); oh.y = pack16(h[2],h[3]);
        oh.z = pack16(h[4],h[5]); oh.w = pack16(h[6],h[7]);
        ol.x = pack16(l[0],l[1]); ol.y = pack16(l[2],l[3]);
        ol.z = pack16(l[4],l[5]); ol.w = pack16(l[6],l[7]);
        *(uint4*)(g_Vhi + base + g * 8) = oh;
        *(uint4*)(g_Vlo + base + g * 8) = ol;
    }
}

// Kernel 3c: o_w -> bf16 hi/lo arrays
__global__ __launch_bounds__(256) void owsplit_kernel(const float* __restrict__ ow)
{
    const int i = blockIdx.x * 256 + threadIdx.x;   // float4 index
    float4 v = ((const float4*)ow)[i];
    uint16_t h[4], l[4];
    split_bf(v.x, h[0], l[0]); split_bf(v.y, h[1], l[1]);
    split_bf(v.z, h[2], l[2]); split_bf(v.w, h[3], l[3]);
    ((uint2*)g_OWh)[i] = make_uint2(pack16(h[0],h[1]), pack16(h[2],h[3]));
    ((uint2*)g_OWl)[i] = make_uint2(pack16(l[0],l[1]), pack16(l[2],l[3]));
}

// ===========================================================================
// Kernel 4: PV — 128-thread CTAs, M=64(q) tile, warp grid 2x2.
// Unnormalized masked weights w = (l>cut)?2^(l-m):u; inline z2; 1/z2 epilogue.
// ===========================================================================
__global__ __launch_bounds__(128) void pv_mma_kernel()
{
    __shared__ __align__(16) __nv_bfloat16 sAhi[64 * TSTRIDE];
    __shared__ __align__(16) __nv_bfloat16 sAlo[64 * TSTRIDE];
    __shared__ __align__(16) __nv_bfloat16 sBhi[64 * TSTRIDE];
    __shared__ __align__(16) __nv_bfloat16 sBlo[64 * TSTRIDE];
    __shared__ float4 s_stats[64];
    __shared__ float s_z2[64][2];

    const int tid = threadIdx.x;
    const int lane = tid & 31, wid = tid >> 5;
    const int wm = wid & 1, wn = wid >> 1;
    const int bh = blockIdx.y;
    const int q0 = blockIdx.x * 64;

    if (tid < 64) s_stats[tid] = g_stats[(size_t)bh * SS + q0 + tid];

    const int ar = tid >> 1;                 // 0..63 (q row)
    const int ac = (tid & 1) * 16;           // col half within chunk
    const float* Lrow = g_L + ((size_t)bh * SS + q0 + ar) * SS + ac;
    const int vr = tid >> 1;                 // 0..63 (hd row)
    const int vgc = (tid & 1) * 16;          // col half within chunk
    const __nv_bfloat16* Vhrow = g_Vhi + ((size_t)bh * HD + vr) * SS + vgc;
    const __nv_bfloat16* Vlrow = g_Vlo + ((size_t)bh * HD + vr) * SS + vgc;

    const uint32_t aHiB = smem_u32(sAhi), aLoB = smem_u32(sAlo);
    const uint32_t bHiB = smem_u32(sBhi), bLoB = smem_u32(sBlo);
    const int a_row = wm * 32 + ((lane >> 3) & 1) * 8 + (lane & 7);
    const int a_kadd = ((lane >> 4) & 1) * 8;
    const int b_row = wn * 32 + ((lane >> 4) & 1) * 8 + (lane & 7);
    const int b_kadd = ((lane >> 3) & 1) * 8;

    float acc[2][4][4];
    #pragma unroll
    for (int i = 0; i < 2; i++)
        #pragma unroll
        for (int j = 0; j < 4; j++)
            #pragma unroll
            for (int r = 0; r < 4; r++) acc[i][j][r] = 0.f;

    float4 lreg[4];
    uint4 vh0, vh1, vl0, vl1;
    #pragma unroll
    for (int j = 0; j < 4; ++j) lreg[j] = *(const float4*)(Lrow + j * 4);
    vh0 = *(const uint4*)Vhrow;        vh1 = *(const uint4*)(Vhrow + 8);
    vl0 = *(const uint4*)Vlrow;        vl1 = *(const uint4*)(Vlrow + 8);
    __syncthreads();   // stats visible
    const float4 st = s_stats[ar];   // {m2, cut2, 0, u}

    float z2a = 0.f, z2b = 0.f;

    for (int c = 0; c < 64; ++c) {
        __syncthreads();
        // store V tiles first (cheap, retires early)
        *(uint4*)(sBhi + vr * TSTRIDE + vgc)     = vh0;
        *(uint4*)(sBhi + vr * TSTRIDE + vgc + 8) = vh1;
        *(uint4*)(sBlo + vr * TSTRIDE + vgc)     = vl0;
        *(uint4*)(sBlo + vr * TSTRIDE + vgc + 8) = vl1;
        {
            const float* lv = (const float*)lreg;
            uint16_t hi16[16], lo16[16];
            float wv[16];
            #pragma unroll
            for (int j = 0; j < 16; ++j) {
                const float l = lv[j];
                const float w = (l > st.y) ? ex2(l - st.x) : st.w;
                wv[j] = w;
                split_bf(w, hi16[j], lo16[j]);
            }
            #pragma unroll
            for (int j = 0; j < 8; ++j) { z2a += wv[j]; z2b += wv[j + 8]; }
            uint32_t off = (uint32_t)(ar * TSTRIDE + ac);
            uint4 u;
            u.x = pack16(hi16[0],hi16[1]);  u.y = pack16(hi16[2],hi16[3]);
            u.z = pack16(hi16[4],hi16[5]);  u.w = pack16(hi16[6],hi16[7]);
            *(uint4*)(sAhi + off) = u;
            u.x = pack16(hi16[8],hi16[9]);  u.y = pack16(hi16[10],hi16[11]);
            u.z = pack16(hi16[12],hi16[13]);u.w = pack16(hi16[14],hi16[15]);
            *(uint4*)(sAhi + off + 8) = u;
            u.x = pack16(lo16[0],lo16[1]);  u.y = pack16(lo16[2],lo16[3]);
            u.z = pack16(lo16[4],lo16[5]);  u.w = pack16(lo16[6],lo16[7]);
            *(uint4*)(sAlo + off) = u;
            u.x = pack16(lo16[8],lo16[9]);  u.y = pack16(lo16[10],lo16[11]);
            u.z = pack16(lo16[12],lo16[13]);u.w = pack16(lo16[14],lo16[15]);
            *(uint4*)(sAlo + off + 8) = u;
        }

        if (c + 1 < 64) {
            #pragma unroll
            for (int j = 0; j < 4; ++j)
                lreg[j] = *(const float4*)(Lrow + (c + 1) * 32 + j * 4);
            vh0 = *(const uint4*)(Vhrow + (c + 1) * 32);
            vh1 = *(const uint4*)(Vhrow + (c + 1) * 32 + 8);
            vl0 = *(const uint4*)(Vlrow + (c + 1) * 32);
            vl1 = *(const uint4*)(Vlrow + (c + 1) * 32 + 8);
        }
        __syncthreads();

        #pragma unroll
        for (int ks = 0; ks < 2; ++ks) {
            const int kc = ks * 16;
            uint32_t ah[2][4], al[2][4], bhf[2][4], blf[2][4];
            #pragma unroll
            for (int i = 0; i < 2; ++i) {
                uint32_t ro = (uint32_t)((a_row + i * 16) * TSTRIDE + kc + a_kadd) * 2;
                ldsm4(ah[i], aHiB + ro);
                ldsm4(al[i], aLoB + ro);
            }
            #pragma unroll
            for (int p = 0; p < 2; ++p) {
                uint32_t ro = (uint32_t)((b_row + p * 16) * TSTRIDE + kc + b_kadd) * 2;
                ldsm4(bhf[p], bHiB + ro);
                ldsm4(blf[p], bLoB + ro);
            }
            #pragma unroll
            for (int i = 0; i < 2; ++i)
                #pragma unroll
                for (int jn = 0; jn < 4; ++jn) {
                    const int p = jn >> 1, q = (jn & 1) * 2;
                    mma16816(acc[i][jn], ah[i], bhf[p][q], bhf[p][q + 1]);
                    mma16816(acc[i][jn], ah[i], blf[p][q], blf[p][q + 1]);
                    mma16816(acc[i][jn], al[i], bhf[p][q], bhf[p][q + 1]);
                }
        }
    }

    // per-row z2 combine
    s_z2[ar][tid & 1] = z2a + z2b;
    __syncthreads();

    const int b = bh >> 4, h = bh & (HH - 1);
    const int g = lane >> 2, t = lane & 3;
    #pragma unroll
    for (int i = 0; i < 2; ++i) {
        #pragma unroll
        for (int half = 0; half < 2; ++half) {
            const int rl = wm * 32 + i * 16 + g + half * 8;
            const float inv = 1.0f / (s_z2[rl][0] + s_z2[rl][1]);
            const int q = q0 + rl;
            #pragma unroll
            for (int jn = 0; jn < 4; ++jn) {
                const int n = wn * 32 + jn * 8 + 2 * t;
                const float x0 = acc[i][jn][half * 2 + 0] * inv;
                const float x1 = acc[i][jn][half * 2 + 1] * inv;
                uint16_t h0, l0, h1, l1;
                split_bf(x0, h0, l0);
                split_bf(x1, h1, l1);
                const size_t base = (size_t)(b * SS + q) * DD + h * HD + n;
                *(uint32_t*)(g_valsH + base) = pack16(h0, h1);
                *(uint32_t*)(g_valsL + base) = pack16(l0, l1);
            }
        }
    }
}

// ===========================================================================
// Kernel 5: O projection — 128-thread CTAs, M=64 tile, 3 products over K=1024.
// ===========================================================================
__global__ __launch_bounds__(128) void oproj_mma_kernel(
    const float* __restrict__ ob, float* __restrict__ out)
{
    __shared__ __align__(16) __nv_bfloat16 sAh[64 * TSTRIDE];
    __shared__ __align__(16) __nv_bfloat16 sAl[64 * TSTRIDE];
    __shared__ __align__(16) __nv_bfloat16 sBh[64 * TSTRIDE];
    __shared__ __align__(16) __nv_bfloat16 sBl[64 * TSTRIDE];

    const int tid = threadIdx.x;
    const int lane = tid & 31, wid = tid >> 5;
    const int wm = wid & 1, wn = wid >> 1;
    const int m0 = blockIdx.x * 64;
    const int n0 = blockIdx.y * 64;

    const int ar = tid >> 1;
    const int ac = (tid & 1) * 16;
    const __nv_bfloat16* AhRow = g_valsH + (size_t)(m0 + ar) * DD + ac;
    const __nv_bfloat16* AlRow = g_valsL + (size_t)(m0 + ar) * DD + ac;
    const __nv_bfloat16* BhRow = g_OWh + (size_t)(n0 + ar) * DD + ac;
    const __nv_bfloat16* BlRow = g_OWl + (size_t)(n0 + ar) * DD + ac;

    const uint32_t ahB = smem_u32(sAh), alB = smem_u32(sAl);
    const uint32_t bhB = smem_u32(sBh), blB = smem_u32(sBl);
    const int a_row = wm * 32 + ((lane >> 3) & 1) * 8 + (lane & 7);
    const int a_kadd = ((lane >> 4) & 1) * 8;
    const int b_row = wn * 32 + ((lane >> 4) & 1) * 8 + (lane & 7);
    const int b_kadd = ((lane >> 3) & 1) * 8;

    float acc[2][4][4];
    #pragma unroll
    for (int i = 0; i < 2; i++)
        #pragma unroll
        for (int j = 0; j < 4; j++)
            #pragma unroll
            for (int r = 0; r < 4; r++) acc[i][j][r] = 0.f;

    uint4 a0h, a1h, a0l, a1l, b0h, b1h, b0l, b1l;
    a0h = *(const uint4*)(AhRow);      a1h = *(const uint4*)(AhRow + 8);
    a0l = *(const uint4*)(AlRow);      a1l = *(const uint4*)(AlRow + 8);
    b0h = *(const uint4*)(BhRow);      b1h = *(const uint4*)(BhRow + 8);
    b0l = *(const uint4*)(BlRow);      b1l = *(const uint4*)(BlRow + 8);

    const int NCH = DD / 32;   // 32
    for (int c = 0; c < NCH; ++c) {
        __syncthreads();
        *(uint4*)(sAh + ar * TSTRIDE + ac)     = a0h;
        *(uint4*)(sAh + ar * TSTRIDE + ac + 8) = a1h;
        *(uint4*)(sAl + ar * TSTRIDE + ac)     = a0l;
        *(uint4*)(sAl + ar * TSTRIDE + ac + 8) = a1l;
        *(uint4*)(sBh + ar * TSTRIDE + ac)     = b0h;
        *(uint4*)(sBh + ar * TSTRIDE + ac + 8) = b1h;
        *(uint4*)(sBl + ar * TSTRIDE + ac)     = b0l;
        *(uint4*)(sBl + ar * TSTRIDE + ac + 8) = b1l;
        if (c + 1 < NCH) {
            a0h = *(const uint4*)(AhRow + (c + 1) * 32);
            a1h = *(const uint4*)(AhRow + (c + 1) * 32 + 8);
            a0l = *(const uint4*)(AlRow + (c + 1) * 32);
            a1l = *(const uint4*)(AlRow + (c + 1) * 32 + 8);
            b0h = *(const uint4*)(BhRow + (c + 1) * 32);
            b1h = *(const uint4*)(BhRow + (c + 1) * 32 + 8);
            b0l = *(const uint4*)(BlRow + (c + 1) * 32);
            b1l = *(const uint4*)(BlRow + (c + 1) * 32 + 8);
        }
        __syncthreads();

        #pragma unroll
        for (int ks = 0; ks < 2; ++ks) {
            const int kc = ks * 16;
            uint32_t fah[2][4], fal[2][4], fbh[2][4], fbl[2][4];
            #pragma unroll
            for (int i = 0; i < 2; ++i) {
                uint32_t ro = (uint32_t)((a_row + i * 16) * TSTRIDE + kc + a_kadd) * 2;
                ldsm4(fah[i], ahB + ro);
                ldsm4(fal[i], alB + ro);
            }
            #pragma unroll
            for (int p = 0; p < 2; ++p) {
                uint32_t ro = (uint32_t)((b_row + p * 16) * TSTRIDE + kc + b_kadd) * 2;
                ldsm4(fbh[p], bhB + ro);
                ldsm4(fbl[p], blB + ro);
            }
            #pragma unroll
            for (int i = 0; i < 2; ++i)
                #pragma unroll
                for (int jn = 0; jn < 4; ++jn) {
                    const int p = jn >> 1, q = (jn & 1) * 2;
                    mma16816(acc[i][jn], fah[i], fbh[p][q], fbh[p][q + 1]);
                    mma16816(acc[i][jn], fah[i], fbl[p][q], fbl[p][q + 1]);
                    mma16816(acc[i][jn], fal[i], fbh[p][q], fbh[p][q + 1]);
                }
        }
    }

    const int g = lane >> 2, t = lane & 3;
    #pragma unroll
    for (int i = 0; i < 2; ++i) {
        #pragma unroll
        for (int jn = 0; jn < 4; ++jn) {
            const int n = n0 + wn * 32 + jn * 8 + 2 * t;
            const float bx = ob[n], by = ob[n + 1];
            #pragma unroll
            for (int half = 0; half < 2; ++half) {
                const int m = m0 + wm * 32 + i * 16 + g + half * 8;
                float2 v;
                v.x = acc[i][jn][half * 2 + 0] + bx;
                v.y = acc[i][jn][half * 2 + 1] + by;
                *(float2*)(out + (size_t)m * DD + n) = v;
            }
        }
    }
}

// ===========================================================================
extern "C" void kernel_launch(void* const* d_in, const int* in_sizes, int n_in,
                              void* d_out, int out_size)
{
    const float *x = nullptr, *thr = nullptr, *qkvw = nullptr,
                *qkvb = nullptr, *ow = nullptr, *ob = nullptr;
    for (int i = 0; i < n_in; ++i) {
        const float* p = (const float*)d_in[i];
        switch (in_sizes[i]) {
            case MROWS * DD:   x = p;    break;
            case HH:           thr = p;  break;
            case E3D * DD:     qkvw = p; break;
            case E3D:          qkvb = p; break;
            case DD * DD:      ow = p;   break;
            case DD:           ob = p;   break;
        }
    }
    float* out = (float*)d_out;

    __half *Xh, *Xm, *Xl, *Wh, *Wm, *Wl;
    cudaGetSymbolAddress((void**)&Xh, g_Xh);
    cudaGetSymbolAddress((void**)&Xm, g_Xm);
    cudaGetSymbolAddress((void**)&Xl, g_Xl);
    cudaGetSymbolAddress((void**)&Wh, g_Wh);
    cudaGetSymbolAddress((void**)&Wm, g_Wm);
    cudaGetSymbolAddress((void**)&Wl, g_Wl);

    cudaFuncSetAttribute(qkv_mma_kernel, cudaFuncAttributeMaxDynamicSharedMemorySize, QKV_SMEM);
    cudaFuncSetAttribute(logits_mma_kernel, cudaFuncAttributeMaxDynamicSharedMemorySize, LG_SMEM);

    // launch index 3 (qkv) is the one ncu profiles — keep qkv there.
    split3_kernel<<<(MROWS * DD) / 1024, 256>>>(x, Xh, Xm, Xl);
    split3_kernel<<<(E3D * DD) / 1024, 256>>>(qkvw, Wh, Wm, Wl);
    owsplit_kernel<<<(DD * DD) / 1024, 256>>>(ow);
    qkv_mma_kernel<<<dim3(MROWS / 64, E3D / 64), 128, QKV_SMEM>>>(qkvb);
    vsplit_kernel<<<dim3(SS / 128, BH), 256>>>();
    logits_mma_kernel<<<dim3(SS / 64, SS / 64, BH), 128, LG_SMEM>>>();
    combine_kernel<<<(BH * SS) / 8, 256>>>(thr);
    pv_mma_kernel<<<dim3(SS / 64, BH), 128>>>();
    oproj_mma_kernel<<<dim3(MROWS / 64, DD / 64), 128>>>(ob, out);
}

// round 13
// speedup vs baseline: 1.0552x; 1.0552x over previous
#include <cuda_runtime.h>
#include <cuda_bf16.h>
#include <cuda_fp16.h>
#include <cstdint>

// Problem constants
#define BB 2
#define SS 2048
#define DD 1024
#define HH 16
#define HD 64
#define BH (BB*HH)          // 32
#define MROWS (BB*SS)       // 4096
#define E3D (3*DD)          // 3072

// Scratch (device globals; allocation-free kernel_launch)
__device__ float g_V[(size_t)BH * SS * HD];            // 16 MB
__device__ float g_L[(size_t)BH * SS * SS];            // 512 MB (log2-domain logits)
__device__ float2 g_part[(size_t)BH * SS * 32];        // per (row, ntile) {m_loc, z_loc}
__device__ float4 g_stats[(size_t)BH * SS];            // {m2, cut2, 0, u}
__device__ __half g_Xh[(size_t)MROWS * DD];            // x 3-term split
__device__ __half g_Xm[(size_t)MROWS * DD];
__device__ __half g_Xl[(size_t)MROWS * DD];
__device__ __half g_Wh[(size_t)E3D * DD];              // qkv_w 3-term split
__device__ __half g_Wm[(size_t)E3D * DD];
__device__ __half g_Wl[(size_t)E3D * DD];
__device__ __half g_Qh[(size_t)BH * SS * HD];          // Q 3-term [bh][s][hd]
__device__ __half g_Qm[(size_t)BH * SS * HD];
__device__ __half g_Ql[(size_t)BH * SS * HD];
__device__ __half g_Kh[(size_t)BH * SS * HD];          // K 3-term
__device__ __half g_Km[(size_t)BH * SS * HD];
__device__ __half g_Kl[(size_t)BH * SS * HD];
__device__ __nv_bfloat16 g_Vhi[(size_t)BH * HD * SS];  // V^T hi [bh][hd][s]
__device__ __nv_bfloat16 g_Vlo[(size_t)BH * HD * SS];  // V^T lo
__device__ __nv_bfloat16 g_valsH[(size_t)MROWS * DD];  // attn out hi [m][d]
__device__ __nv_bfloat16 g_valsL[(size_t)MROWS * DD];  // attn out lo
__device__ __nv_bfloat16 g_OWh[(size_t)DD * DD];       // o_w hi [n][k]
__device__ __nv_bfloat16 g_OWl[(size_t)DD * DD];       // o_w lo

#define C_G1 2.44140625e-4f            // 2^-12
#define C_G2 5.9604644775390625e-8f    // 2^-24
#define LOG2E 1.44269504088896340736f

// ===========================================================================
// Helpers
// ===========================================================================
__device__ __forceinline__ uint32_t smem_u32(const void* p) {
    uint32_t a;
    asm("{ .reg .u64 t; cvta.to.shared.u64 t, %1; cvt.u32.u64 %0, t; }" : "=r"(a) : "l"(p));
    return a;
}
__device__ __forceinline__ uint32_t pack16(uint16_t a, uint16_t b) {
    return (uint32_t)a | ((uint32_t)b << 16);
}
__device__ __forceinline__ float ex2(float x) {
    float r; asm("ex2.approx.f32 %0, %1;" : "=f"(r) : "f"(x)); return r;
}
__device__ __forceinline__ void split_bf(float x, uint16_t& h, uint16_t& l) {
    __nv_bfloat16 hb = __float2bfloat16(x);
    float r = x - __bfloat162float(hb);
    __nv_bfloat16 lb = __float2bfloat16(r);
    h = *reinterpret_cast<uint16_t*>(&hb);
    l = *reinterpret_cast<uint16_t*>(&lb);
}
// scaled 3-term fp16 split: x = h + m*2^-12 + l*2^-24 (+O(x*2^-35))
__device__ __forceinline__ void split3(float x, uint16_t& h, uint16_t& m, uint16_t& l) {
    __half a = __float2half_rn(x);
    float r1 = x - __half2float(a);
    __half b = __float2half_rn(r1 * 4096.0f);
    float r2 = r1 - __half2float(b) * C_G1;
    __half c = __float2half_rn(r2 * 16777216.0f);
    h = *reinterpret_cast<uint16_t*>(&a);
    m = *reinterpret_cast<uint16_t*>(&b);
    l = *reinterpret_cast<uint16_t*>(&c);
}
__device__ __forceinline__ void ldsm4(uint32_t* r, uint32_t addr) {
    asm volatile("ldmatrix.sync.aligned.m8n8.x4.shared.b16 {%0,%1,%2,%3}, [%4];"
                 : "=r"(r[0]), "=r"(r[1]), "=r"(r[2]), "=r"(r[3]) : "r"(addr));
}
__device__ __forceinline__ void mma16816(float* c, const uint32_t* a,
                                         uint32_t b0, uint32_t b1) {
    asm volatile(
        "mma.sync.aligned.m16n8k16.row.col.f32.bf16.bf16.f32 "
        "{%0,%1,%2,%3}, {%4,%5,%6,%7}, {%8,%9}, {%0,%1,%2,%3};"
        : "+f"(c[0]), "+f"(c[1]), "+f"(c[2]), "+f"(c[3])
        : "r"(a[0]), "r"(a[1]), "r"(a[2]), "r"(a[3]), "r"(b0), "r"(b1));
}
__device__ __forceinline__ void mma16816h(float* c, const uint32_t* a,
                                          uint32_t b0, uint32_t b1) {
    asm volatile(
        "mma.sync.aligned.m16n8k16.row.col.f32.f16.f16.f32 "
        "{%0,%1,%2,%3}, {%4,%5,%6,%7}, {%8,%9}, {%0,%1,%2,%3};"
        : "+f"(c[0]), "+f"(c[1]), "+f"(c[2]), "+f"(c[3])
        : "r"(a[0]), "r"(a[1]), "r"(a[2]), "r"(a[3]), "r"(b0), "r"(b1));
}
__device__ __forceinline__ void cp16(uint32_t dst, const void* src) {
    asm volatile("cp.async.cg.shared.global [%0], [%1], 16;" :: "r"(dst), "l"(src));
}
#define CP_COMMIT() asm volatile("cp.async.commit_group;")
#define CP_WAIT1()  asm volatile("cp.async.wait_group 1;")
#define CP_WAIT0()  asm volatile("cp.async.wait_group 0;")

#define TSTRIDE 40   // 16-bit elems per smem row for chunked tiles (80B)
#define LSTRIDE 72   // 16-bit elems per smem row for full-K logits tiles (144B)

// ===========================================================================
// Kernel 0: fp32 -> scaled 3-term fp16 split. 4 elems/thread.
// ===========================================================================
__global__ __launch_bounds__(256) void split3_kernel(
    const float* __restrict__ src, __half* __restrict__ dh,
    __half* __restrict__ dm, __half* __restrict__ dl)
{
    const int i = blockIdx.x * 256 + threadIdx.x;
    float4 v = ((const float4*)src)[i];
    uint16_t h[4], m[4], l[4];
    split3(v.x, h[0], m[0], l[0]); split3(v.y, h[1], m[1], l[1]);
    split3(v.z, h[2], m[2], l[2]); split3(v.w, h[3], m[3], l[3]);
    ((uint2*)dh)[i] = make_uint2(pack16(h[0],h[1]), pack16(h[2],h[3]));
    ((uint2*)dm)[i] = make_uint2(pack16(m[0],m[1]), pack16(m[2],m[3]));
    ((uint2*)dl)[i] = make_uint2(pack16(l[0],l[1]), pack16(l[2],l[3]));
}

// ===========================================================================
// Kernel 1: QKV projection via 3-term fp16 HMMA — 128-thread CTAs, M=64 tile.
// G0 drained every 2 chunks (RZ chain length 4; ~+2e-5 rel err, halves drain cost).
// ===========================================================================
#define QKV_BUF 30720   // A 3*5120 | B 3*5120
#define QKV_SMEM (2*QKV_BUF)
__global__ __launch_bounds__(128) void qkv_mma_kernel(const float* __restrict__ bias)
{
    extern __shared__ __align__(16) char qsm[];
    const int tid = threadIdx.x;
    const int lane = tid & 31, wid = tid >> 5;
    const int wm = wid & 1, wn = wid >> 1;
    const int m0 = blockIdx.x * 64;
    const int e0 = blockIdx.y * 64;
    const int typ = (e0 >> 6) % 3;          // 0=Q, 1=K, 2=V
    const bool vmode = (typ == 2);
    const int head = e0 / 192;

    const uint32_t sb0 = smem_u32(qsm);
    const int rA = tid >> 1;                 // 0..63
    const int gA = (tid & 1) * 2;            // 16B-group base

    const __half* XA[3] = { g_Xh, g_Xm, g_Xl };
    const __half* WB[3] = { g_Wh, g_Wm, g_Wl };
    const uint32_t Aoff[3] = { 0u, 5120u, 10240u };
    const uint32_t Boff[3] = { 15360u, 20480u, 25600u };
    const int nTiles = vmode ? 2 : 3;

    const int a_row = wm * 32 + ((lane >> 3) & 1) * 8 + (lane & 7);
    const int a_kadd = ((lane >> 4) & 1) * 8;
    const int b_row = wn * 32 + ((lane >> 4) & 1) * 8 + (lane & 7);
    const int b_kadd = ((lane >> 3) & 1) * 8;

    float acc0[2][4][4], acc1[2][4][4], acc2[2][4][4], gr0[2][4][4];
    #pragma unroll
    for (int i = 0; i < 2; i++)
        #pragma unroll
        for (int j = 0; j < 4; j++)
            #pragma unroll
            for (int r = 0; r < 4; r++) {
                acc0[i][j][r]=0.f; acc1[i][j][r]=0.f; acc2[i][j][r]=0.f; gr0[i][j][r]=0.f;
            }

    auto issue = [&](int c, int bb) {
        const uint32_t sb = sb0 + bb * QKV_BUF;
        #pragma unroll
        for (int T = 0; T < 3; ++T) {
            if (T >= nTiles) break;
            const __half* srcA = XA[T] + (size_t)(m0 + rA) * DD + c * 32 + gA * 8;
            uint32_t dstA = sb + Aoff[T] + (uint32_t)(rA * TSTRIDE + gA * 8) * 2;
            cp16(dstA, srcA);
            cp16(dstA + 16, srcA + 8);
            const __half* srcB = WB[T] + (size_t)(e0 + rA) * DD + c * 32 + gA * 8;
            uint32_t dstB = sb + Boff[T] + (uint32_t)(rA * TSTRIDE + gA * 8) * 2;
            cp16(dstB, srcB);
            cp16(dstB + 16, srcB + 8);
        }
        CP_COMMIT();
    };

    issue(0, 0);
    const int NCH = DD / 32;   // 32
    for (int c = 0; c < NCH; ++c) {
        if (c + 1 < NCH) { issue(c + 1, (c + 1) & 1); CP_WAIT1(); }
        else             { CP_WAIT0(); }
        __syncthreads();

        const uint32_t sb = sb0 + (c & 1) * QKV_BUF;
        #pragma unroll
        for (int ks = 0; ks < 2; ++ks) {
            const int kc = ks * 16;
            uint32_t fah[2][4], fam[2][4], fal[2][4];
            uint32_t fbh[2][4], fbm[2][4], fbl[2][4];
            #pragma unroll
            for (int i = 0; i < 2; ++i) {
                uint32_t ro = (uint32_t)((a_row + i * 16) * TSTRIDE + kc + a_kadd) * 2;
                ldsm4(fah[i], sb + Aoff[0] + ro);
                ldsm4(fam[i], sb + Aoff[1] + ro);
                if (!vmode) ldsm4(fal[i], sb + Aoff[2] + ro);
            }
            #pragma unroll
            for (int p = 0; p < 2; ++p) {
                uint32_t ro = (uint32_t)((b_row + p * 16) * TSTRIDE + kc + b_kadd) * 2;
                ldsm4(fbh[p], sb + Boff[0] + ro);
                ldsm4(fbm[p], sb + Boff[1] + ro);
                if (!vmode) ldsm4(fbl[p], sb + Boff[2] + ro);
            }
            #pragma unroll
            for (int i = 0; i < 2; ++i)
                #pragma unroll
                for (int jn = 0; jn < 4; ++jn) {
                    const int p = jn >> 1, q = (jn & 1) * 2;
                    mma16816h(acc0[i][jn], fah[i], fbh[p][q], fbh[p][q + 1]);
                    mma16816h(acc1[i][jn], fah[i], fbm[p][q], fbm[p][q + 1]);
                    mma16816h(acc1[i][jn], fam[i], fbh[p][q], fbh[p][q + 1]);
                    if (!vmode) {
                        mma16816h(acc2[i][jn], fah[i], fbl[p][q], fbl[p][q + 1]);
                        mma16816h(acc2[i][jn], fam[i], fbm[p][q], fbm[p][q + 1]);
                        mma16816h(acc2[i][jn], fal[i], fbh[p][q], fbh[p][q + 1]);
                    }
                }
        }
        // drain G0 every 2 chunks (RZ chain length 4)
        if ((c & 1) || (c == NCH - 1)) {
            #pragma unroll
            for (int i = 0; i < 2; ++i)
                #pragma unroll
                for (int jn = 0; jn < 4; ++jn)
                    #pragma unroll
                    for (int r = 0; r < 4; ++r) {
                        gr0[i][jn][r] += acc0[i][jn][r];
                        acc0[i][jn][r] = 0.f;
                    }
        }
        __syncthreads();
    }

    // epilogue
    const int g = lane >> 2, t = lane & 3;
    #pragma unroll
    for (int i = 0; i < 2; ++i) {
        #pragma unroll
        for (int jn = 0; jn < 4; ++jn) {
            const int nn = wn * 32 + jn * 8 + 2 * t;     // hd (even)
            const int e = e0 + nn;
            const float be0 = bias[e], be1 = bias[e + 1];
            #pragma unroll
            for (int half = 0; half < 2; ++half) {
                const int m = m0 + wm * 32 + i * 16 + g + half * 8;
                const int r0 = half * 2, r1 = half * 2 + 1;
                const float x0 = gr0[i][jn][r0] + C_G1 * acc1[i][jn][r0] + C_G2 * acc2[i][jn][r0] + be0;
                const float x1 = gr0[i][jn][r1] + C_G1 * acc1[i][jn][r1] + C_G2 * acc2[i][jn][r1] + be1;
                const int b = m >> 11, s = m & (SS - 1);
                const size_t base = (((size_t)(b * HH + head) * SS) + s) * HD + nn;
                if (typ == 0) {
                    uint16_t h0,m0_,l0,h1,m1,l1;
                    split3(x0, h0, m0_, l0); split3(x1, h1, m1, l1);
                    *(uint32_t*)(g_Qh + base) = pack16(h0, h1);
                    *(uint32_t*)(g_Qm + base) = pack16(m0_, m1);
                    *(uint32_t*)(g_Ql + base) = pack16(l0, l1);
                } else if (typ == 1) {
                    uint16_t h0,m0_,l0,h1,m1,l1;
                    split3(x0, h0, m0_, l0); split3(x1, h1, m1, l1);
                    *(uint32_t*)(g_Kh + base) = pack16(h0, h1);
                    *(uint32_t*)(g_Km + base) = pack16(m0_, m1);
                    *(uint32_t*)(g_Kl + base) = pack16(l0, l1);
                } else {
                    *(float2*)(g_V + base) = make_float2(x0, x1);
                }
            }
        }
    }
}

// ===========================================================================
// Kernel 2: logits via 3-term fp16 HMMA — 128-thread CTAs, M=64(q) x N=64.
// ===========================================================================
#define LG_SMEM 55296
__global__ __launch_bounds__(128) void logits_mma_kernel()
{
    extern __shared__ __align__(16) char lsm[];
    const int tid = threadIdx.x;
    const int lane = tid & 31, wid = tid >> 5;
    const int wm = wid & 1, wn = wid >> 1;
    const int bh = blockIdx.z;
    const int q0 = blockIdx.x * 64;
    const int n0 = blockIdx.y * 64;

    const uint32_t sb = smem_u32(lsm);
    const uint32_t Aoff[3] = { 0u, 9216u, 18432u };
    const uint32_t Boff[3] = { 27648u, 36864u, 46080u };
    const __half* QA[3] = { g_Qh, g_Qm, g_Ql };
    const __half* KB[3] = { g_Kh, g_Km, g_Kl };

    #pragma unroll
    for (int it = 0; it < 4; ++it) {
        const int idx = tid + it * 128;          // 0..511
        const int r = idx >> 3, gg = idx & 7;
        #pragma unroll
        for (int T = 0; T < 3; ++T) {
            cp16(sb + Aoff[T] + (uint32_t)(r * LSTRIDE + gg * 8) * 2,
                 QA[T] + ((size_t)bh * SS + q0 + r) * HD + gg * 8);
            cp16(sb + Boff[T] + (uint32_t)(r * LSTRIDE + gg * 8) * 2,
                 KB[T] + ((size_t)bh * SS + n0 + r) * HD + gg * 8);
        }
    }
    CP_COMMIT();
    CP_WAIT0();
    __syncthreads();

    const int a_row = wm * 32 + ((lane >> 3) & 1) * 8 + (lane & 7);
    const int a_kadd = ((lane >> 4) & 1) * 8;
    const int b_row = wn * 32 + ((lane >> 4) & 1) * 8 + (lane & 7);
    const int b_kadd = ((lane >> 3) & 1) * 8;

    float acc0[2][4][4], acc1[2][4][4], acc2[2][4][4], gr0[2][4][4];
    #pragma unroll
    for (int i = 0; i < 2; i++)
        #pragma unroll
        for (int j = 0; j < 4; j++)
            #pragma unroll
            for (int r = 0; r < 4; r++) {
                acc0[i][j][r]=0.f; acc1[i][j][r]=0.f; acc2[i][j][r]=0.f; gr0[i][j][r]=0.f;
            }

    #pragma unroll
    for (int ks = 0; ks < 4; ++ks) {
        const int kc = ks * 16;
        uint32_t fah[2][4], fam[2][4], fal[2][4];
        uint32_t fbh[2][4], fbm[2][4], fbl[2][4];
        #pragma unroll
        for (int i = 0; i < 2; ++i) {
            uint32_t ro = (uint32_t)((a_row + i * 16) * LSTRIDE + kc + a_kadd) * 2;
            ldsm4(fah[i], sb + Aoff[0] + ro);
            ldsm4(fam[i], sb + Aoff[1] + ro);
            ldsm4(fal[i], sb + Aoff[2] + ro);
        }
        #pragma unroll
        for (int p = 0; p < 2; ++p) {
            uint32_t ro = (uint32_t)((b_row + p * 16) * LSTRIDE + kc + b_kadd) * 2;
            ldsm4(fbh[p], sb + Boff[0] + ro);
            ldsm4(fbm[p], sb + Boff[1] + ro);
            ldsm4(fbl[p], sb + Boff[2] + ro);
        }
        #pragma unroll
        for (int i = 0; i < 2; ++i)
            #pragma unroll
            for (int jn = 0; jn < 4; ++jn) {
                const int p = jn >> 1, q = (jn & 1) * 2;
                mma16816h(acc0[i][jn], fah[i], fbh[p][q], fbh[p][q + 1]);
                mma16816h(acc1[i][jn], fah[i], fbm[p][q], fbm[p][q + 1]);
                mma16816h(acc1[i][jn], fam[i], fbh[p][q], fbh[p][q + 1]);
                mma16816h(acc2[i][jn], fah[i], fbl[p][q], fbl[p][q + 1]);
                mma16816h(acc2[i][jn], fam[i], fbm[p][q], fbm[p][q + 1]);
                mma16816h(acc2[i][jn], fal[i], fbh[p][q], fbh[p][q + 1]);
            }
        // drain G0 every kstep (RZ chain length 1)
        #pragma unroll
        for (int i = 0; i < 2; ++i)
            #pragma unroll
            for (int jn = 0; jn < 4; ++jn)
                #pragma unroll
                for (int r = 0; r < 4; ++r) {
                    gr0[i][jn][r] += acc0[i][jn][r];
                    acc0[i][jn][r] = 0.f;
                }
    }

    // epilogue: store L (log2 domain) + per-row-tile partial stats
    __syncthreads();                       // tiles dead; reuse lsm for partials
    float2* s_part = (float2*)lsm;         // [64][8]
    float* Lb = g_L + (size_t)bh * SS * SS;
    const float scl = 0.125f * LOG2E;
    const int g = lane >> 2, t = lane & 3;
    #pragma unroll
    for (int i = 0; i < 2; ++i) {
        #pragma unroll
        for (int half = 0; half < 2; ++half) {
            const int rl = wm * 32 + i * 16 + g + half * 8;
            const int q = q0 + rl;
            const int r0 = half * 2, r1 = half * 2 + 1;
            float lv[8];
            #pragma unroll
            for (int jn = 0; jn < 4; ++jn) {
                const int n = n0 + wn * 32 + jn * 8 + 2 * t;
                float2 v;
                v.x = (gr0[i][jn][r0] + C_G1 * acc1[i][jn][r0] + C_G2 * acc2[i][jn][r0]) * scl;
                v.y = (gr0[i][jn][r1] + C_G1 * acc1[i][jn][r1] + C_G2 * acc2[i][jn][r1]) * scl;
                *(float2*)(Lb + (size_t)q * SS + n) = v;
                lv[jn * 2] = v.x; lv[jn * 2 + 1] = v.y;
            }
            float mloc = lv[0];
            #pragma unroll
            for (int j = 1; j < 8; ++j) mloc = fmaxf(mloc, lv[j]);
            float zloc = 0.f;
            #pragma unroll
            for (int j = 0; j < 8; ++j) zloc += ex2(lv[j] - mloc);
            s_part[rl * 8 + wn * 4 + t] = make_float2(mloc, zloc);
        }
    }
    __syncthreads();
    if (tid < 64) {
        float2 pp[8];
        float m = -3.4e38f;
        #pragma unroll
        for (int j = 0; j < 8; ++j) {
            pp[j] = s_part[tid * 8 + j];
            m = fmaxf(m, pp[j].x);
        }
        float z = 0.f;
        #pragma unroll
        for (int j = 0; j < 8; ++j) z += pp[j].y * ex2(pp[j].x - m);
        g_part[((size_t)bh * SS + q0 + tid) * 32 + (n0 >> 6)] = make_float2(m, z);
    }
}

// ===========================================================================
// Kernel 3: combine partials -> {m2, cut2, 0, u}. One warp per row.
// ===========================================================================
__global__ __launch_bounds__(256) void combine_kernel(const float* __restrict__ thrs)
{
    const int row = blockIdx.x * 8 + (threadIdx.x >> 5);
    const int lane = threadIdx.x & 31;
    float2 p = g_part[(size_t)row * 32 + lane];
    float m = p.x;
    #pragma unroll
    for (int o = 16; o > 0; o >>= 1) m = fmaxf(m, __shfl_xor_sync(0xffffffffu, m, o));
    float z = p.y * ex2(p.x - m);
    #pragma unroll
    for (int o = 16; o > 0; o >>= 1) z += __shfl_xor_sync(0xffffffffu, z, o);
    if (lane == 0) {
        const int h = (row >> 11) & (HH - 1);
        const float tz = thrs[h] * z;
        float4 st;
        if (tz >= 1.0f) {
            st.x = 0.f; st.y = __int_as_float(0x7f800000);   // +inf
            st.z = 0.f; st.w = 1.0f;                          // uniform: w=1 everywhere
        } else {
            st.x = m; st.y = m + log2f(tz); st.z = 0.f; st.w = 0.f;
        }
        g_stats[row] = st;
    }
}

// ===========================================================================
// Kernel 3b: V transpose + bf16 hi/lo split: g_Vhi/g_Vlo [bh][hd][s]
// ===========================================================================
__global__ __launch_bounds__(256) void vsplit_kernel()
{
    __shared__ float t[64][132];
    const int bh = blockIdx.y, s0 = blockIdx.x * 128;
    const float* Vb = g_V + (size_t)bh * SS * HD;
    const int sl = threadIdx.x >> 1;
    const int hh = (threadIdx.x & 1) * 32;
    #pragma unroll
    for (int j = 0; j < 8; ++j) {
        float4 v = *(const float4*)(Vb + (size_t)(s0 + sl) * HD + hh + j * 4);
        t[hh + j*4 + 0][sl] = v.x; t[hh + j*4 + 1][sl] = v.y;
        t[hh + j*4 + 2][sl] = v.z; t[hh + j*4 + 3][sl] = v.w;
    }
    __syncthreads();
    const int row = threadIdx.x >> 2;
    const int q = (threadIdx.x & 3) * 32;
    const size_t base = ((size_t)bh * HD + row) * SS + s0 + q;
    #pragma unroll
    for (int g = 0; g < 4; ++g) {
        const float* src = &t[row][q + g * 8];
        uint16_t h[8], l[8];
        #pragma unroll
        for (int j = 0; j < 8; ++j) split_bf(src[j], h[j], l[j]);
        uint4 oh, ol;
        oh.x = pack16(h[0],h[1]); oh.y = pack16(h[2],h[3]);
        oh.z = pack16(h[4],h[5]); oh.w = pack16(h[6],h[7]);
        ol.x = pack16(l[0],l[1]); ol.y = pack16(l[2],l[3]);
        ol.z = pack16(l[4],l[5]); ol.w = pack16(l[6],l[7]);
        *(uint4*)(g_Vhi + base + g * 8) = oh;
        *(uint4*)(g_Vlo + base + g * 8) = ol;
    }
}

// Kernel 3c: o_w -> bf16 hi/lo arrays
__global__ __launch_bounds__(256) void owsplit_kernel(const float* __restrict__ ow)
{
    const int i = blockIdx.x * 256 + threadIdx.x;   // float4 index
    float4 v = ((const float4*)ow)[i];
    uint16_t h[4], l[4];
    split_bf(v.x, h[0], l[0]); split_bf(v.y, h[1], l[1]);
    split_bf(v.z, h[2], l[2]); split_bf(v.w, h[3], l[3]);
    ((uint2*)g_OWh)[i] = make_uint2(pack16(h[0],h[1]), pack16(h[2],h[3]));
    ((uint2*)g_OWl)[i] = make_uint2(pack16(l[0],l[1]), pack16(l[2],l[3]));
}

// ===========================================================================
// Kernel 4: PV — 256-thread CTAs (R11-proven), M=128(q) tile.
// Unnormalized masked weights w = (l>cut)?2^(l-m):u; inline z2; 1/z2 epilogue.
// ===========================================================================
__global__ __launch_bounds__(256) void pv_mma_kernel()
{
    __shared__ __align__(16) __nv_bfloat16 sAhi[128 * TSTRIDE];
    __shared__ __align__(16) __nv_bfloat16 sAlo[128 * TSTRIDE];
    __shared__ __align__(16) __nv_bfloat16 sBhi[64 * TSTRIDE];
    __shared__ __align__(16) __nv_bfloat16 sBlo[64 * TSTRIDE];
    __shared__ float4 s_stats[128];
    __shared__ float s_z2[128][2];

    const int tid = threadIdx.x;
    const int lane = tid & 31, wid = tid >> 5;
    const int wm = wid & 3, wn = wid >> 2;
    const int bh = blockIdx.y;
    const int q0 = blockIdx.x * 128;

    if (tid < 128) s_stats[tid] = g_stats[(size_t)bh * SS + q0 + tid];

    const int ar = tid >> 1;
    const int ac = (tid & 1) * 16;
    const float* Lrow = g_L + ((size_t)bh * SS + q0 + ar) * SS + ac;
    const int vr = tid >> 2;
    const int vc = (tid & 3) * 8;
    const __nv_bfloat16* Vhrow = g_Vhi + ((size_t)bh * HD + vr) * SS + vc;
    const __nv_bfloat16* Vlrow = g_Vlo + ((size_t)bh * HD + vr) * SS + vc;

    const uint32_t aHiB = smem_u32(sAhi), aLoB = smem_u32(sAlo);
    const uint32_t bHiB = smem_u32(sBhi), bLoB = smem_u32(sBlo);
    const int a_row = wm * 32 + ((lane >> 3) & 1) * 8 + (lane & 7);
    const int a_kadd = ((lane >> 4) & 1) * 8;
    const int b_row = wn * 32 + ((lane >> 4) & 1) * 8 + (lane & 7);
    const int b_kadd = ((lane >> 3) & 1) * 8;

    float acc[2][4][4];
    #pragma unroll
    for (int i = 0; i < 2; i++)
        #pragma unroll
        for (int j = 0; j < 4; j++)
            #pragma unroll
            for (int r = 0; r < 4; r++) acc[i][j][r] = 0.f;

    float4 lreg[4];
    uint4 vh, vl;
    #pragma unroll
    for (int j = 0; j < 4; ++j) lreg[j] = *(const float4*)(Lrow + j * 4);
    vh = *(const uint4*)Vhrow;
    vl = *(const uint4*)Vlrow;
    __syncthreads();   // stats visible
    const float4 st = s_stats[ar];   // {m2, cut2, 0, u}

    float z2a = 0.f, z2b = 0.f;

    for (int c = 0; c < 64; ++c) {
        __syncthreads();
        // store V tiles first (cheap, retires early)
        *(uint4*)(sBhi + vr * TSTRIDE + vc) = vh;
        *(uint4*)(sBlo + vr * TSTRIDE + vc) = vl;
        {
            const float* lv = (const float*)lreg;
            uint16_t hi16[16], lo16[16];
            float wv[16];
            #pragma unroll
            for (int j = 0; j < 16; ++j) {
                const float l = lv[j];
                const float w = (l > st.y) ? ex2(l - st.x) : st.w;
                wv[j] = w;
                split_bf(w, hi16[j], lo16[j]);
            }
            #pragma unroll
            for (int j = 0; j < 8; ++j) { z2a += wv[j]; z2b += wv[j + 8]; }
            uint32_t off = (uint32_t)(ar * TSTRIDE + ac);
            uint4 u;
            u.x = pack16(hi16[0],hi16[1]);  u.y = pack16(hi16[2],hi16[3]);
            u.z = pack16(hi16[4],hi16[5]);  u.w = pack16(hi16[6],hi16[7]);
            *(uint4*)(sAhi + off) = u;
            u.x = pack16(hi16[8],hi16[9]);  u.y = pack16(hi16[10],hi16[11]);
            u.z = pack16(hi16[12],hi16[13]);u.w = pack16(hi16[14],hi16[15]);
            *(uint4*)(sAhi + off + 8) = u;
            u.x = pack16(lo16[0],lo16[1]);  u.y = pack16(lo16[2],lo16[3]);
            u.z = pack16(lo16[4],lo16[5]);  u.w = pack16(lo16[6],lo16[7]);
            *(uint4*)(sAlo + off) = u;
            u.x = pack16(lo16[8],lo16[9]);  u.y = pack16(lo16[10],lo16[11]);
            u.z = pack16(lo16[12],lo16[13]);u.w = pack16(lo16[14],lo16[15]);
            *(uint4*)(sAlo + off + 8) = u;
        }

        if (c + 1 < 64) {
            #pragma unroll
            for (int j = 0; j < 4; ++j)
                lreg[j] = *(const float4*)(Lrow + (c + 1) * 32 + j * 4);
            vh = *(const uint4*)(Vhrow + (c + 1) * 32);
            vl = *(const uint4*)(Vlrow + (c + 1) * 32);
        }
        __syncthreads();

        #pragma unroll
        for (int ks = 0; ks < 2; ++ks) {
            const int kc = ks * 16;
            uint32_t ah[2][4], al[2][4], bhf[2][4], blf[2][4];
            #pragma unroll
            for (int i = 0; i < 2; ++i) {
                uint32_t ro = (uint32_t)((a_row + i * 16) * TSTRIDE + kc + a_kadd) * 2;
                ldsm4(ah[i], aHiB + ro);
                ldsm4(al[i], aLoB + ro);
            }
            #pragma unroll
            for (int p = 0; p < 2; ++p) {
                uint32_t ro = (uint32_t)((b_row + p * 16) * TSTRIDE + kc + b_kadd) * 2;
                ldsm4(bhf[p], bHiB + ro);
                ldsm4(blf[p], bLoB + ro);
            }
            #pragma unroll
            for (int i = 0; i < 2; ++i)
                #pragma unroll
                for (int jn = 0; jn < 4; ++jn) {
                    const int p = jn >> 1, q = (jn & 1) * 2;
                    mma16816(acc[i][jn], ah[i], bhf[p][q], bhf[p][q + 1]);
                    mma16816(acc[i][jn], ah[i], blf[p][q], blf[p][q + 1]);
                    mma16816(acc[i][jn], al[i], bhf[p][q], bhf[p][q + 1]);
                }
        }
    }

    // per-row z2 combine
    s_z2[ar][tid & 1] = z2a + z2b;
    __syncthreads();

    const int b = bh >> 4, h = bh & (HH - 1);
    const int g = lane >> 2, t = lane & 3;
    #pragma unroll
    for (int i = 0; i < 2; ++i) {
        #pragma unroll
        for (int half = 0; half < 2; ++half) {
            const int rl = wm * 32 + i * 16 + g + half * 8;
            const float inv = 1.0f / (s_z2[rl][0] + s_z2[rl][1]);
            const int q = q0 + rl;
            #pragma unroll
            for (int jn = 0; jn < 4; ++jn) {
                const int n = wn * 32 + jn * 8 + 2 * t;
                const float x0 = acc[i][jn][half * 2 + 0] * inv;
                const float x1 = acc[i][jn][half * 2 + 1] * inv;
                uint16_t h0, l0, h1, l1;
                split_bf(x0, h0, l0);
                split_bf(x1, h1, l1);
                const size_t base = (size_t)(b * SS + q) * DD + h * HD + n;
                *(uint32_t*)(g_valsH + base) = pack16(h0, h1);
                *(uint32_t*)(g_valsL + base) = pack16(l0, l1);
            }
        }
    }
}

// ===========================================================================
// Kernel 5: O projection — 256-thread CTAs (R11-proven), M=128 tile.
// ===========================================================================
__global__ __launch_bounds__(256) void oproj_mma_kernel(
    const float* __restrict__ ob, float* __restrict__ out)
{
    __shared__ __align__(16) __nv_bfloat16 sAh[128 * TSTRIDE];
    __shared__ __align__(16) __nv_bfloat16 sAl[128 * TSTRIDE];
    __shared__ __align__(16) __nv_bfloat16 sBh[64 * TSTRIDE];
    __shared__ __align__(16) __nv_bfloat16 sBl[64 * TSTRIDE];

    const int tid = threadIdx.x;
    const int lane = tid & 31, wid = tid >> 5;
    const int wm = wid & 3, wn = wid >> 2;
    const int m0 = blockIdx.x * 128;
    const int n0 = blockIdx.y * 64;

    const int ar = tid >> 1;
    const int ac = (tid & 1) * 16;
    const __nv_bfloat16* AhRow = g_valsH + (size_t)(m0 + ar) * DD + ac;
    const __nv_bfloat16* AlRow = g_valsL + (size_t)(m0 + ar) * DD + ac;
    const int vr = tid >> 2;
    const int vc = (tid & 3) * 8;
    const __nv_bfloat16* BhRow = g_OWh + (size_t)(n0 + vr) * DD + vc;
    const __nv_bfloat16* BlRow = g_OWl + (size_t)(n0 + vr) * DD + vc;

    const uint32_t ahB = smem_u32(sAh), alB = smem_u32(sAl);
    const uint32_t bhB = smem_u32(sBh), blB = smem_u32(sBl);
    const int a_row = wm * 32 + ((lane >> 3) & 1) * 8 + (lane & 7);
    const int a_kadd = ((lane >> 4) & 1) * 8;
    const int b_row = wn * 32 + ((lane >> 4) & 1) * 8 + (lane & 7);
    const int b_kadd = ((lane >> 3) & 1) * 8;

    float acc[2][4][4];
    #pragma unroll
    for (int i = 0; i < 2; i++)
        #pragma unroll
        for (int j = 0; j < 4; j++)
            #pragma unroll
            for (int r = 0; r < 4; r++) acc[i][j][r] = 0.f;

    uint4 a0h, a1h, a0l, a1l, b0h, b0l;
    a0h = *(const uint4*)(AhRow);      a1h = *(const uint4*)(AhRow + 8);
    a0l = *(const uint4*)(AlRow);      a1l = *(const uint4*)(AlRow + 8);
    b0h = *(const uint4*)(BhRow);      b0l = *(const uint4*)(BlRow);

    const int NCH = DD / 32;   // 32
    for (int c = 0; c < NCH; ++c) {
        __syncthreads();
        *(uint4*)(sAh + ar * TSTRIDE + ac)     = a0h;
        *(uint4*)(sAh + ar * TSTRIDE + ac + 8) = a1h;
        *(uint4*)(sAl + ar * TSTRIDE + ac)     = a0l;
        *(uint4*)(sAl + ar * TSTRIDE + ac + 8) = a1l;
        *(uint4*)(sBh + vr * TSTRIDE + vc) = b0h;
        *(uint4*)(sBl + vr * TSTRIDE + vc) = b0l;
        if (c + 1 < NCH) {
            a0h = *(const uint4*)(AhRow + (c + 1) * 32);
            a1h = *(const uint4*)(AhRow + (c + 1) * 32 + 8);
            a0l = *(const uint4*)(AlRow + (c + 1) * 32);
            a1l = *(const uint4*)(AlRow + (c + 1) * 32 + 8);
            b0h = *(const uint4*)(BhRow + (c + 1) * 32);
            b0l = *(const uint4*)(BlRow + (c + 1) * 32);
        }
        __syncthreads();

        #pragma unroll
        for (int ks = 0; ks < 2; ++ks) {
            const int kc = ks * 16;
            uint32_t fah[2][4], fal[2][4], fbh[2][4], fbl[2][4];
            #pragma unroll
            for (int i = 0; i < 2; ++i) {
                uint32_t ro = (uint32_t)((a_row + i * 16) * TSTRIDE + kc + a_kadd) * 2;
                ldsm4(fah[i], ahB + ro);
                ldsm4(fal[i], alB + ro);
            }
            #pragma unroll
            for (int p = 0; p < 2; ++p) {
                uint32_t ro = (uint32_t)((b_row + p * 16) * TSTRIDE + kc + b_kadd) * 2;
                ldsm4(fbh[p], bhB + ro);
                ldsm4(fbl[p], blB + ro);
            }
            #pragma unroll
            for (int i = 0; i < 2; ++i)
                #pragma unroll
                for (int jn = 0; jn < 4; ++jn) {
                    const int p = jn >> 1, q = (jn & 1) * 2;
                    mma16816(acc[i][jn], fah[i], fbh[p][q], fbh[p][q + 1]);
                    mma16816(acc[i][jn], fah[i], fbl[p][q], fbl[p][q + 1]);
                    mma16816(acc[i][jn], fal[i], fbh[p][q], fbh[p][q + 1]);
                }
        }
    }

    const int g = lane >> 2, t = lane & 3;
    #pragma unroll
    for (int i = 0; i < 2; ++i) {
        #pragma unroll
        for (int jn = 0; jn < 4; ++jn) {
            const int n = n0 + wn * 32 + jn * 8 + 2 * t;
            const float bx = ob[n], by = ob[n + 1];
            #pragma unroll
            for (int half = 0; half < 2; ++half) {
                const int m = m0 + wm * 32 + i * 16 + g + half * 8;
                float2 v;
                v.x = acc[i][jn][half * 2 + 0] + bx;
                v.y = acc[i][jn][half * 2 + 1] + by;
                *(float2*)(out + (size_t)m * DD + n) = v;
            }
        }
    }
}

// ===========================================================================
extern "C" void kernel_launch(void* const* d_in, const int* in_sizes, int n_in,
                              void* d_out, int out_size)
{
    const float *x = nullptr, *thr = nullptr, *qkvw = nullptr,
                *qkvb = nullptr, *ow = nullptr, *ob = nullptr;
    for (int i = 0; i < n_in; ++i) {
        const float* p = (const float*)d_in[i];
        switch (in_sizes[i]) {
            case MROWS * DD:   x = p;    break;
            case HH:           thr = p;  break;
            case E3D * DD:     qkvw = p; break;
            case E3D:          qkvb = p; break;
            case DD * DD:      ow = p;   break;
            case DD:           ob = p;   break;
        }
    }
    float* out = (float*)d_out;

    __half *Xh, *Xm, *Xl, *Wh, *Wm, *Wl;
    cudaGetSymbolAddress((void**)&Xh, g_Xh);
    cudaGetSymbolAddress((void**)&Xm, g_Xm);
    cudaGetSymbolAddress((void**)&Xl, g_Xl);
    cudaGetSymbolAddress((void**)&Wh, g_Wh);
    cudaGetSymbolAddress((void**)&Wm, g_Wm);
    cudaGetSymbolAddress((void**)&Wl, g_Wl);

    cudaFuncSetAttribute(qkv_mma_kernel, cudaFuncAttributeMaxDynamicSharedMemorySize, QKV_SMEM);
    cudaFuncSetAttribute(logits_mma_kernel, cudaFuncAttributeMaxDynamicSharedMemorySize, LG_SMEM);

    // launch index 3 (qkv) is the one ncu profiles — keep qkv there.
    split3_kernel<<<(MROWS * DD) / 1024, 256>>>(x, Xh, Xm, Xl);
    split3_kernel<<<(E3D * DD) / 1024, 256>>>(qkvw, Wh, Wm, Wl);
    owsplit_kernel<<<(DD * DD) / 1024, 256>>>(ow);
    qkv_mma_kernel<<<dim3(MROWS / 64, E3D / 64), 128, QKV_SMEM>>>(qkvb);
    vsplit_kernel<<<dim3(SS / 128, BH), 256>>>();
    logits_mma_kernel<<<dim3(SS / 64, SS / 64, BH), 128, LG_SMEM>>>();
    combine_kernel<<<(BH * SS) / 8, 256>>>(thr);
    pv_mma_kernel<<<dim3(SS / 128, BH), 256>>>();
    oproj_mma_kernel<<<dim3(MROWS / 128, DD / 64), 256>>>(ob, out);
}

// round 14
// speedup vs baseline: 1.0809x; 1.0243x over previous
#include <cuda_runtime.h>
#include <cuda_bf16.h>
#include <cuda_fp16.h>
#include <cstdint>

// Problem constants
#define BB 2
#define SS 2048
#define DD 1024
#define HH 16
#define HD 64
#define BH (BB*HH)          // 32
#define MROWS (BB*SS)       // 4096
#define E3D (3*DD)          // 3072

// Scratch (device globals; allocation-free kernel_launch)
__device__ float g_V[(size_t)BH * SS * HD];            // 16 MB
__device__ float g_L[(size_t)BH * SS * SS];            // 512 MB (log2-domain logits)
__device__ float2 g_part[(size_t)BH * SS * 32];        // per (row, ntile) {m_loc, z_loc}
__device__ float4 g_stats[(size_t)BH * SS];            // {m2, cut2, 0, u}
__device__ __half g_Xh[(size_t)MROWS * DD];            // x 3-term split
__device__ __half g_Xm[(size_t)MROWS * DD];
__device__ __half g_Xl[(size_t)MROWS * DD];
__device__ __half g_Wh[(size_t)E3D * DD];              // qkv_w 3-term split
__device__ __half g_Wm[(size_t)E3D * DD];
__device__ __half g_Wl[(size_t)E3D * DD];
__device__ __half g_Qh[(size_t)BH * SS * HD];          // Q 3-term [bh][s][hd]
__device__ __half g_Qm[(size_t)BH * SS * HD];
__device__ __half g_Ql[(size_t)BH * SS * HD];
__device__ __half g_Kh[(size_t)BH * SS * HD];          // K 3-term
__device__ __half g_Km[(size_t)BH * SS * HD];
__device__ __half g_Kl[(size_t)BH * SS * HD];
__device__ __nv_bfloat16 g_Vhi[(size_t)BH * HD * SS];  // V^T hi [bh][hd][s]
__device__ __nv_bfloat16 g_Vlo[(size_t)BH * HD * SS];  // V^T lo
__device__ __nv_bfloat16 g_valsH[(size_t)MROWS * DD];  // attn out hi [m][d]
__device__ __nv_bfloat16 g_valsL[(size_t)MROWS * DD];  // attn out lo
__device__ __nv_bfloat16 g_OWh[(size_t)DD * DD];       // o_w hi [n][k]
__device__ __nv_bfloat16 g_OWl[(size_t)DD * DD];       // o_w lo

#define C_G1 2.44140625e-4f            // 2^-12
#define C_G2 5.9604644775390625e-8f    // 2^-24
#define LOG2E 1.44269504088896340736f

// ===========================================================================
// Helpers
// ===========================================================================
__device__ __forceinline__ uint32_t smem_u32(const void* p) {
    uint32_t a;
    asm("{ .reg .u64 t; cvta.to.shared.u64 t, %1; cvt.u32.u64 %0, t; }" : "=r"(a) : "l"(p));
    return a;
}
__device__ __forceinline__ uint32_t pack16(uint16_t a, uint16_t b) {
    return (uint32_t)a | ((uint32_t)b << 16);
}
__device__ __forceinline__ float ex2(float x) {
    float r; asm("ex2.approx.f32 %0, %1;" : "=f"(r) : "f"(x)); return r;
}
__device__ __forceinline__ void split_bf(float x, uint16_t& h, uint16_t& l) {
    __nv_bfloat16 hb = __float2bfloat16(x);
    float r = x - __bfloat162float(hb);
    __nv_bfloat16 lb = __float2bfloat16(r);
    h = *reinterpret_cast<uint16_t*>(&hb);
    l = *reinterpret_cast<uint16_t*>(&lb);
}
// scaled 3-term fp16 split: x = h + m*2^-12 + l*2^-24 (+O(x*2^-35))
__device__ __forceinline__ void split3(float x, uint16_t& h, uint16_t& m, uint16_t& l) {
    __half a = __float2half_rn(x);
    float r1 = x - __half2float(a);
    __half b = __float2half_rn(r1 * 4096.0f);
    float r2 = r1 - __half2float(b) * C_G1;
    __half c = __float2half_rn(r2 * 16777216.0f);
    h = *reinterpret_cast<uint16_t*>(&a);
    m = *reinterpret_cast<uint16_t*>(&b);
    l = *reinterpret_cast<uint16_t*>(&c);
}
__device__ __forceinline__ void ldsm4(uint32_t* r, uint32_t addr) {
    asm volatile("ldmatrix.sync.aligned.m8n8.x4.shared.b16 {%0,%1,%2,%3}, [%4];"
                 : "=r"(r[0]), "=r"(r[1]), "=r"(r[2]), "=r"(r[3]) : "r"(addr));
}
__device__ __forceinline__ void mma16816(float* c, const uint32_t* a,
                                         uint32_t b0, uint32_t b1) {
    asm volatile(
        "mma.sync.aligned.m16n8k16.row.col.f32.bf16.bf16.f32 "
        "{%0,%1,%2,%3}, {%4,%5,%6,%7}, {%8,%9}, {%0,%1,%2,%3};"
        : "+f"(c[0]), "+f"(c[1]), "+f"(c[2]), "+f"(c[3])
        : "r"(a[0]), "r"(a[1]), "r"(a[2]), "r"(a[3]), "r"(b0), "r"(b1));
}
__device__ __forceinline__ void mma16816h(float* c, const uint32_t* a,
                                          uint32_t b0, uint32_t b1) {
    asm volatile(
        "mma.sync.aligned.m16n8k16.row.col.f32.f16.f16.f32 "
        "{%0,%1,%2,%3}, {%4,%5,%6,%7}, {%8,%9}, {%0,%1,%2,%3};"
        : "+f"(c[0]), "+f"(c[1]), "+f"(c[2]), "+f"(c[3])
        : "r"(a[0]), "r"(a[1]), "r"(a[2]), "r"(a[3]), "r"(b0), "r"(b1));
}
__device__ __forceinline__ void cp16(uint32_t dst, const void* src) {
    asm volatile("cp.async.cg.shared.global [%0], [%1], 16;" :: "r"(dst), "l"(src));
}
#define CP_COMMIT() asm volatile("cp.async.commit_group;")
#define CP_WAIT1()  asm volatile("cp.async.wait_group 1;")
#define CP_WAIT0()  asm volatile("cp.async.wait_group 0;")

#define TSTRIDE 40   // 16-bit elems per smem row for chunked tiles (80B)
#define LSTRIDE 72   // 16-bit elems per smem row for full-K logits tiles (144B)

// ===========================================================================
// Kernel 0: fp32 -> scaled 3-term fp16 split. 4 elems/thread.
// ===========================================================================
__global__ __launch_bounds__(256) void split3_kernel(
    const float* __restrict__ src, __half* __restrict__ dh,
    __half* __restrict__ dm, __half* __restrict__ dl)
{
    const int i = blockIdx.x * 256 + threadIdx.x;
    float4 v = ((const float4*)src)[i];
    uint16_t h[4], m[4], l[4];
    split3(v.x, h[0], m[0], l[0]); split3(v.y, h[1], m[1], l[1]);
    split3(v.z, h[2], m[2], l[2]); split3(v.w, h[3], m[3], l[3]);
    ((uint2*)dh)[i] = make_uint2(pack16(h[0],h[1]), pack16(h[2],h[3]));
    ((uint2*)dm)[i] = make_uint2(pack16(m[0],m[1]), pack16(m[2],m[3]));
    ((uint2*)dl)[i] = make_uint2(pack16(l[0],l[1]), pack16(l[2],l[3]));
}

// ===========================================================================
// Kernel 1: QKV projection via 3-term fp16 HMMA — 128-thread CTAs, M=64 tile.
// (exact R11 form: drain every chunk, RZ chain length 2)
// ===========================================================================
#define QKV_BUF 30720   // A 3*5120 | B 3*5120
#define QKV_SMEM (2*QKV_BUF)
__global__ __launch_bounds__(128) void qkv_mma_kernel(const float* __restrict__ bias)
{
    extern __shared__ __align__(16) char qsm[];
    const int tid = threadIdx.x;
    const int lane = tid & 31, wid = tid >> 5;
    const int wm = wid & 1, wn = wid >> 1;
    const int m0 = blockIdx.x * 64;
    const int e0 = blockIdx.y * 64;
    const int typ = (e0 >> 6) % 3;          // 0=Q, 1=K, 2=V
    const bool vmode = (typ == 2);
    const int head = e0 / 192;

    const uint32_t sb0 = smem_u32(qsm);
    const int rA = tid >> 1;                 // 0..63
    const int gA = (tid & 1) * 2;            // 16B-group base

    const __half* XA[3] = { g_Xh, g_Xm, g_Xl };
    const __half* WB[3] = { g_Wh, g_Wm, g_Wl };
    const uint32_t Aoff[3] = { 0u, 5120u, 10240u };
    const uint32_t Boff[3] = { 15360u, 20480u, 25600u };
    const int nTiles = vmode ? 2 : 3;

    const int a_row = wm * 32 + ((lane >> 3) & 1) * 8 + (lane & 7);
    const int a_kadd = ((lane >> 4) & 1) * 8;
    const int b_row = wn * 32 + ((lane >> 4) & 1) * 8 + (lane & 7);
    const int b_kadd = ((lane >> 3) & 1) * 8;

    float acc0[2][4][4], acc1[2][4][4], acc2[2][4][4], gr0[2][4][4];
    #pragma unroll
    for (int i = 0; i < 2; i++)
        #pragma unroll
        for (int j = 0; j < 4; j++)
            #pragma unroll
            for (int r = 0; r < 4; r++) {
                acc0[i][j][r]=0.f; acc1[i][j][r]=0.f; acc2[i][j][r]=0.f; gr0[i][j][r]=0.f;
            }

    auto issue = [&](int c, int bb) {
        const uint32_t sb = sb0 + bb * QKV_BUF;
        #pragma unroll
        for (int T = 0; T < 3; ++T) {
            if (T >= nTiles) break;
            const __half* srcA = XA[T] + (size_t)(m0 + rA) * DD + c * 32 + gA * 8;
            uint32_t dstA = sb + Aoff[T] + (uint32_t)(rA * TSTRIDE + gA * 8) * 2;
            cp16(dstA, srcA);
            cp16(dstA + 16, srcA + 8);
            const __half* srcB = WB[T] + (size_t)(e0 + rA) * DD + c * 32 + gA * 8;
            uint32_t dstB = sb + Boff[T] + (uint32_t)(rA * TSTRIDE + gA * 8) * 2;
            cp16(dstB, srcB);
            cp16(dstB + 16, srcB + 8);
        }
        CP_COMMIT();
    };

    issue(0, 0);
    const int NCH = DD / 32;   // 32
    for (int c = 0; c < NCH; ++c) {
        if (c + 1 < NCH) { issue(c + 1, (c + 1) & 1); CP_WAIT1(); }
        else             { CP_WAIT0(); }
        __syncthreads();

        const uint32_t sb = sb0 + (c & 1) * QKV_BUF;
        #pragma unroll
        for (int ks = 0; ks < 2; ++ks) {
            const int kc = ks * 16;
            uint32_t fah[2][4], fam[2][4], fal[2][4];
            uint32_t fbh[2][4], fbm[2][4], fbl[2][4];
            #pragma unroll
            for (int i = 0; i < 2; ++i) {
                uint32_t ro = (uint32_t)((a_row + i * 16) * TSTRIDE + kc + a_kadd) * 2;
                ldsm4(fah[i], sb + Aoff[0] + ro);
                ldsm4(fam[i], sb + Aoff[1] + ro);
                if (!vmode) ldsm4(fal[i], sb + Aoff[2] + ro);
            }
            #pragma unroll
            for (int p = 0; p < 2; ++p) {
                uint32_t ro = (uint32_t)((b_row + p * 16) * TSTRIDE + kc + b_kadd) * 2;
                ldsm4(fbh[p], sb + Boff[0] + ro);
                ldsm4(fbm[p], sb + Boff[1] + ro);
                if (!vmode) ldsm4(fbl[p], sb + Boff[2] + ro);
            }
            #pragma unroll
            for (int i = 0; i < 2; ++i)
                #pragma unroll
                for (int jn = 0; jn < 4; ++jn) {
                    const int p = jn >> 1, q = (jn & 1) * 2;
                    mma16816h(acc0[i][jn], fah[i], fbh[p][q], fbh[p][q + 1]);
                    mma16816h(acc1[i][jn], fah[i], fbm[p][q], fbm[p][q + 1]);
                    mma16816h(acc1[i][jn], fam[i], fbh[p][q], fbh[p][q + 1]);
                    if (!vmode) {
                        mma16816h(acc2[i][jn], fah[i], fbl[p][q], fbl[p][q + 1]);
                        mma16816h(acc2[i][jn], fam[i], fbm[p][q], fbm[p][q + 1]);
                        mma16816h(acc2[i][jn], fal[i], fbh[p][q], fbh[p][q + 1]);
                    }
                }
        }
        // drain G0 (RZ chain length 2) into RN grand accumulator
        #pragma unroll
        for (int i = 0; i < 2; ++i)
            #pragma unroll
            for (int jn = 0; jn < 4; ++jn)
                #pragma unroll
                for (int r = 0; r < 4; ++r) {
                    gr0[i][jn][r] += acc0[i][jn][r];
                    acc0[i][jn][r] = 0.f;
                }
        __syncthreads();
    }

    // epilogue
    const int g = lane >> 2, t = lane & 3;
    #pragma unroll
    for (int i = 0; i < 2; ++i) {
        #pragma unroll
        for (int jn = 0; jn < 4; ++jn) {
            const int nn = wn * 32 + jn * 8 + 2 * t;     // hd (even)
            const int e = e0 + nn;
            const float be0 = bias[e], be1 = bias[e + 1];
            #pragma unroll
            for (int half = 0; half < 2; ++half) {
                const int m = m0 + wm * 32 + i * 16 + g + half * 8;
                const int r0 = half * 2, r1 = half * 2 + 1;
                const float x0 = gr0[i][jn][r0] + C_G1 * acc1[i][jn][r0] + C_G2 * acc2[i][jn][r0] + be0;
                const float x1 = gr0[i][jn][r1] + C_G1 * acc1[i][jn][r1] + C_G2 * acc2[i][jn][r1] + be1;
                const int b = m >> 11, s = m & (SS - 1);
                const size_t base = (((size_t)(b * HH + head) * SS) + s) * HD + nn;
                if (typ == 0) {
                    uint16_t h0,m0_,l0,h1,m1,l1;
                    split3(x0, h0, m0_, l0); split3(x1, h1, m1, l1);
                    *(uint32_t*)(g_Qh + base) = pack16(h0, h1);
                    *(uint32_t*)(g_Qm + base) = pack16(m0_, m1);
                    *(uint32_t*)(g_Ql + base) = pack16(l0, l1);
                } else if (typ == 1) {
                    uint16_t h0,m0_,l0,h1,m1,l1;
                    split3(x0, h0, m0_, l0); split3(x1, h1, m1, l1);
                    *(uint32_t*)(g_Kh + base) = pack16(h0, h1);
                    *(uint32_t*)(g_Km + base) = pack16(m0_, m1);
                    *(uint32_t*)(g_Kl + base) = pack16(l0, l1);
                } else {
                    *(float2*)(g_V + base) = make_float2(x0, x1);
                }
            }
        }
    }
}

// ===========================================================================
// Kernel 2: logits — 128-thread CTAs, M=64(q); Q tile RESIDENT in smem,
// sweeps LG_NB=4 consecutive K n-tiles serially (L2 reload traffic -38%).
// Per-n-tile MMA/drain sequence identical to R11 (numerics unchanged).
// ===========================================================================
#define LG_SMEM 55296
#define LG_NB 4
__global__ __launch_bounds__(128) void logits_mma_kernel()
{
    extern __shared__ __align__(16) char lsm[];
    const int tid = threadIdx.x;
    const int lane = tid & 31, wid = tid >> 5;
    const int wm = wid & 1, wn = wid >> 1;
    const int bh = blockIdx.z;
    const int q0 = blockIdx.x * 64;
    const int nbase = blockIdx.y * (64 * LG_NB);

    const uint32_t sb = smem_u32(lsm);
    const uint32_t Aoff[3] = { 0u, 9216u, 18432u };
    const uint32_t Boff[3] = { 27648u, 36864u, 46080u };
    const __half* QA[3] = { g_Qh, g_Qm, g_Ql };
    const __half* KB[3] = { g_Kh, g_Km, g_Kl };

    // Load Q tiles once (resident for all LG_NB n-tiles)
    #pragma unroll
    for (int it = 0; it < 4; ++it) {
        const int idx = tid + it * 128;          // 0..511
        const int r = idx >> 3, gg = idx & 7;
        #pragma unroll
        for (int T = 0; T < 3; ++T)
            cp16(sb + Aoff[T] + (uint32_t)(r * LSTRIDE + gg * 8) * 2,
                 QA[T] + ((size_t)bh * SS + q0 + r) * HD + gg * 8);
    }
    CP_COMMIT();

    const int a_row = wm * 32 + ((lane >> 3) & 1) * 8 + (lane & 7);
    const int a_kadd = ((lane >> 4) & 1) * 8;
    const int b_row = wn * 32 + ((lane >> 4) & 1) * 8 + (lane & 7);
    const int b_kadd = ((lane >> 3) & 1) * 8;
    const int g = lane >> 2, t = lane & 3;
    const float scl = 0.125f * LOG2E;
    float* Lb = g_L + (size_t)bh * SS * SS;
    float2* s_part = (float2*)(lsm + 27648);   // aliases B region (dead between tiles)

    for (int nt = 0; nt < LG_NB; ++nt) {
        const int n0 = nbase + nt * 64;
        // load this n-tile's K tiles
        #pragma unroll
        for (int it = 0; it < 4; ++it) {
            const int idx = tid + it * 128;
            const int r = idx >> 3, gg = idx & 7;
            #pragma unroll
            for (int T = 0; T < 3; ++T)
                cp16(sb + Boff[T] + (uint32_t)(r * LSTRIDE + gg * 8) * 2,
                     KB[T] + ((size_t)bh * SS + n0 + r) * HD + gg * 8);
        }
        CP_COMMIT();
        CP_WAIT0();
        __syncthreads();

        float acc0[2][4][4], acc1[2][4][4], acc2[2][4][4], gr0[2][4][4];
        #pragma unroll
        for (int i = 0; i < 2; i++)
            #pragma unroll
            for (int j = 0; j < 4; j++)
                #pragma unroll
                for (int r = 0; r < 4; r++) {
                    acc0[i][j][r]=0.f; acc1[i][j][r]=0.f; acc2[i][j][r]=0.f; gr0[i][j][r]=0.f;
                }

        #pragma unroll
        for (int ks = 0; ks < 4; ++ks) {
            const int kc = ks * 16;
            uint32_t fah[2][4], fam[2][4], fal[2][4];
            uint32_t fbh[2][4], fbm[2][4], fbl[2][4];
            #pragma unroll
            for (int i = 0; i < 2; ++i) {
                uint32_t ro = (uint32_t)((a_row + i * 16) * LSTRIDE + kc + a_kadd) * 2;
                ldsm4(fah[i], sb + Aoff[0] + ro);
                ldsm4(fam[i], sb + Aoff[1] + ro);
                ldsm4(fal[i], sb + Aoff[2] + ro);
            }
            #pragma unroll
            for (int p = 0; p < 2; ++p) {
                uint32_t ro = (uint32_t)((b_row + p * 16) * LSTRIDE + kc + b_kadd) * 2;
                ldsm4(fbh[p], sb + Boff[0] + ro);
                ldsm4(fbm[p], sb + Boff[1] + ro);
                ldsm4(fbl[p], sb + Boff[2] + ro);
            }
            #pragma unroll
            for (int i = 0; i < 2; ++i)
                #pragma unroll
                for (int jn = 0; jn < 4; ++jn) {
                    const int p = jn >> 1, q = (jn & 1) * 2;
                    mma16816h(acc0[i][jn], fah[i], fbh[p][q], fbh[p][q + 1]);
                    mma16816h(acc1[i][jn], fah[i], fbm[p][q], fbm[p][q + 1]);
                    mma16816h(acc1[i][jn], fam[i], fbh[p][q], fbh[p][q + 1]);
                    mma16816h(acc2[i][jn], fah[i], fbl[p][q], fbl[p][q + 1]);
                    mma16816h(acc2[i][jn], fam[i], fbm[p][q], fbm[p][q + 1]);
                    mma16816h(acc2[i][jn], fal[i], fbh[p][q], fbh[p][q + 1]);
                }
            // drain G0 every kstep (RZ chain length 1)
            #pragma unroll
            for (int i = 0; i < 2; ++i)
                #pragma unroll
                for (int jn = 0; jn < 4; ++jn)
                    #pragma unroll
                    for (int r = 0; r < 4; ++r) {
                        gr0[i][jn][r] += acc0[i][jn][r];
                        acc0[i][jn][r] = 0.f;
                    }
        }
        __syncthreads();   // all B reads done before s_part overwrites B region

        // epilogue: store L (log2 domain) + per-row-tile partial stats
        #pragma unroll
        for (int i = 0; i < 2; ++i) {
            #pragma unroll
            for (int half = 0; half < 2; ++half) {
                const int rl = wm * 32 + i * 16 + g + half * 8;
                const int q = q0 + rl;
                const int r0 = half * 2, r1 = half * 2 + 1;
                float lv[8];
                #pragma unroll
                for (int jn = 0; jn < 4; ++jn) {
                    const int n = n0 + wn * 32 + jn * 8 + 2 * t;
                    float2 v;
                    v.x = (gr0[i][jn][r0] + C_G1 * acc1[i][jn][r0] + C_G2 * acc2[i][jn][r0]) * scl;
                    v.y = (gr0[i][jn][r1] + C_G1 * acc1[i][jn][r1] + C_G2 * acc2[i][jn][r1]) * scl;
                    *(float2*)(Lb + (size_t)q * SS + n) = v;
                    lv[jn * 2] = v.x; lv[jn * 2 + 1] = v.y;
                }
                float mloc = lv[0];
                #pragma unroll
                for (int j = 1; j < 8; ++j) mloc = fmaxf(mloc, lv[j]);
                float zloc = 0.f;
                #pragma unroll
                for (int j = 0; j < 8; ++j) zloc += ex2(lv[j] - mloc);
                s_part[rl * 8 + wn * 4 + t] = make_float2(mloc, zloc);
            }
        }
        __syncthreads();
        if (tid < 64) {
            float2 pp[8];
            float m = -3.4e38f;
            #pragma unroll
            for (int j = 0; j < 8; ++j) {
                pp[j] = s_part[tid * 8 + j];
                m = fmaxf(m, pp[j].x);
            }
            float z = 0.f;
            #pragma unroll
            for (int j = 0; j < 8; ++j) z += pp[j].y * ex2(pp[j].x - m);
            g_part[((size_t)bh * SS + q0 + tid) * 32 + (n0 >> 6)] = make_float2(m, z);
        }
        __syncthreads();   // s_part reads done before next n-tile's B load
    }
}

// ===========================================================================
// Kernel 3: combine partials -> {m2, cut2, 0, u}. One warp per row.
// ===========================================================================
__global__ __launch_bounds__(256) void combine_kernel(const float* __restrict__ thrs)
{
    const int row = blockIdx.x * 8 + (threadIdx.x >> 5);
    const int lane = threadIdx.x & 31;
    float2 p = g_part[(size_t)row * 32 + lane];
    float m = p.x;
    #pragma unroll
    for (int o = 16; o > 0; o >>= 1) m = fmaxf(m, __shfl_xor_sync(0xffffffffu, m, o));
    float z = p.y * ex2(p.x - m);
    #pragma unroll
    for (int o = 16; o > 0; o >>= 1) z += __shfl_xor_sync(0xffffffffu, z, o);
    if (lane == 0) {
        const int h = (row >> 11) & (HH - 1);
        const float tz = thrs[h] * z;
        float4 st;
        if (tz >= 1.0f) {
            st.x = 0.f; st.y = __int_as_float(0x7f800000);   // +inf
            st.z = 0.f; st.w = 1.0f;                          // uniform: w=1 everywhere
        } else {
            st.x = m; st.y = m + log2f(tz); st.z = 0.f; st.w = 0.f;
        }
        g_stats[row] = st;
    }
}

// ===========================================================================
// Kernel 3b: V transpose + bf16 hi/lo split: g_Vhi/g_Vlo [bh][hd][s]
// ===========================================================================
__global__ __launch_bounds__(256) void vsplit_kernel()
{
    __shared__ float t[64][132];
    const int bh = blockIdx.y, s0 = blockIdx.x * 128;
    const float* Vb = g_V + (size_t)bh * SS * HD;
    const int sl = threadIdx.x >> 1;
    const int hh = (threadIdx.x & 1) * 32;
    #pragma unroll
    for (int j = 0; j < 8; ++j) {
        float4 v = *(const float4*)(Vb + (size_t)(s0 + sl) * HD + hh + j * 4);
        t[hh + j*4 + 0][sl] = v.x; t[hh + j*4 + 1][sl] = v.y;
        t[hh + j*4 + 2][sl] = v.z; t[hh + j*4 + 3][sl] = v.w;
    }
    __syncthreads();
    const int row = threadIdx.x >> 2;
    const int q = (threadIdx.x & 3) * 32;
    const size_t base = ((size_t)bh * HD + row) * SS + s0 + q;
    #pragma unroll
    for (int g = 0; g < 4; ++g) {
        const float* src = &t[row][q + g * 8];
        uint16_t h[8], l[8];
        #pragma unroll
        for (int j = 0; j < 8; ++j) split_bf(src[j], h[j], l[j]);
        uint4 oh, ol;
        oh.x = pack16(h[0],h[1]); oh.y = pack16(h[2],h[3]);
        oh.z = pack16(h[4],h[5]); oh.w = pack16(h[6],h[7]);
        ol.x = pack16(l[0],l[1]); ol.y = pack16(l[2],l[3]);
        ol.z = pack16(l[4],l[5]); ol.w = pack16(l[6],l[7]);
        *(uint4*)(g_Vhi + base + g * 8) = oh;
        *(uint4*)(g_Vlo + base + g * 8) = ol;
    }
}

// Kernel 3c: o_w -> bf16 hi/lo arrays
__global__ __launch_bounds__(256) void owsplit_kernel(const float* __restrict__ ow)
{
    const int i = blockIdx.x * 256 + threadIdx.x;   // float4 index
    float4 v = ((const float4*)ow)[i];
    uint16_t h[4], l[4];
    split_bf(v.x, h[0], l[0]); split_bf(v.y, h[1], l[1]);
    split_bf(v.z, h[2], l[2]); split_bf(v.w, h[3], l[3]);
    ((uint2*)g_OWh)[i] = make_uint2(pack16(h[0],h[1]), pack16(h[2],h[3]));
    ((uint2*)g_OWl)[i] = make_uint2(pack16(l[0],l[1]), pack16(l[2],l[3]));
}

// ===========================================================================
// Kernel 4: PV — 256-thread CTAs (R11-proven), M=128(q) tile.
// Unnormalized masked weights w = (l>cut)?2^(l-m):u; inline z2; 1/z2 epilogue.
// ===========================================================================
__global__ __launch_bounds__(256) void pv_mma_kernel()
{
    __shared__ __align__(16) __nv_bfloat16 sAhi[128 * TSTRIDE];
    __shared__ __align__(16) __nv_bfloat16 sAlo[128 * TSTRIDE];
    __shared__ __align__(16) __nv_bfloat16 sBhi[64 * TSTRIDE];
    __shared__ __align__(16) __nv_bfloat16 sBlo[64 * TSTRIDE];
    __shared__ float4 s_stats[128];
    __shared__ float s_z2[128][2];

    const int tid = threadIdx.x;
    const int lane = tid & 31, wid = tid >> 5;
    const int wm = wid & 3, wn = wid >> 2;
    const int bh = blockIdx.y;
    const int q0 = blockIdx.x * 128;

    if (tid < 128) s_stats[tid] = g_stats[(size_t)bh * SS + q0 + tid];

    const int ar = tid >> 1;
    const int ac = (tid & 1) * 16;
    const float* Lrow = g_L + ((size_t)bh * SS + q0 + ar) * SS + ac;
    const int vr = tid >> 2;
    const int vc = (tid & 3) * 8;
    const __nv_bfloat16* Vhrow = g_Vhi + ((size_t)bh * HD + vr) * SS + vc;
    const __nv_bfloat16* Vlrow = g_Vlo + ((size_t)bh * HD + vr) * SS + vc;

    const uint32_t aHiB = smem_u32(sAhi), aLoB = smem_u32(sAlo);
    const uint32_t bHiB = smem_u32(sBhi), bLoB = smem_u32(sBlo);
    const int a_row = wm * 32 + ((lane >> 3) & 1) * 8 + (lane & 7);
    const int a_kadd = ((lane >> 4) & 1) * 8;
    const int b_row = wn * 32 + ((lane >> 4) & 1) * 8 + (lane & 7);
    const int b_kadd = ((lane >> 3) & 1) * 8;

    float acc[2][4][4];
    #pragma unroll
    for (int i = 0; i < 2; i++)
        #pragma unroll
        for (int j = 0; j < 4; j++)
            #pragma unroll
            for (int r = 0; r < 4; r++) acc[i][j][r] = 0.f;

    float4 lreg[4];
    uint4 vh, vl;
    #pragma unroll
    for (int j = 0; j < 4; ++j) lreg[j] = *(const float4*)(Lrow + j * 4);
    vh = *(const uint4*)Vhrow;
    vl = *(const uint4*)Vlrow;
    __syncthreads();   // stats visible
    const float4 st = s_stats[ar];   // {m2, cut2, 0, u}

    float z2a = 0.f, z2b = 0.f;

    for (int c = 0; c < 64; ++c) {
        __syncthreads();
        // store V tiles first (cheap, retires early)
        *(uint4*)(sBhi + vr * TSTRIDE + vc) = vh;
        *(uint4*)(sBlo + vr * TSTRIDE + vc) = vl;
        {
            const float* lv = (const float*)lreg;
            uint16_t hi16[16], lo16[16];
            float wv[16];
            #pragma unroll
            for (int j = 0; j < 16; ++j) {
                const float l = lv[j];
                const float w = (l > st.y) ? ex2(l - st.x) : st.w;
                wv[j] = w;
                split_bf(w, hi16[j], lo16[j]);
            }
            #pragma unroll
            for (int j = 0; j < 8; ++j) { z2a += wv[j]; z2b += wv[j + 8]; }
            uint32_t off = (uint32_t)(ar * TSTRIDE + ac);
            uint4 u;
            u.x = pack16(hi16[0],hi16[1]);  u.y = pack16(hi16[2],hi16[3]);
            u.z = pack16(hi16[4],hi16[5]);  u.w = pack16(hi16[6],hi16[7]);
            *(uint4*)(sAhi + off) = u;
            u.x = pack16(hi16[8],hi16[9]);  u.y = pack16(hi16[10],hi16[11]);
            u.z = pack16(hi16[12],hi16[13]);u.w = pack16(hi16[14],hi16[15]);
            *(uint4*)(sAhi + off + 8) = u;
            u.x = pack16(lo16[0],lo16[1]);  u.y = pack16(lo16[2],lo16[3]);
            u.z = pack16(lo16[4],lo16[5]);  u.w = pack16(lo16[6],lo16[7]);
            *(uint4*)(sAlo + off) = u;
            u.x = pack16(lo16[8],lo16[9]);  u.y = pack16(lo16[10],lo16[11]);
            u.z = pack16(lo16[12],lo16[13]);u.w = pack16(lo16[14],lo16[15]);
            *(uint4*)(sAlo + off + 8) = u;
        }

        if (c + 1 < 64) {
            #pragma unroll
            for (int j = 0; j < 4; ++j)
                lreg[j] = *(const float4*)(Lrow + (c + 1) * 32 + j * 4);
            vh = *(const uint4*)(Vhrow + (c + 1) * 32);
            vl = *(const uint4*)(Vlrow + (c + 1) * 32);
        }
        __syncthreads();

        #pragma unroll
        for (int ks = 0; ks < 2; ++ks) {
            const int kc = ks * 16;
            uint32_t ah[2][4], al[2][4], bhf[2][4], blf[2][4];
            #pragma unroll
            for (int i = 0; i < 2; ++i) {
                uint32_t ro = (uint32_t)((a_row + i * 16) * TSTRIDE + kc + a_kadd) * 2;
                ldsm4(ah[i], aHiB + ro);
                ldsm4(al[i], aLoB + ro);
            }
            #pragma unroll
            for (int p = 0; p < 2; ++p) {
                uint32_t ro = (uint32_t)((b_row + p * 16) * TSTRIDE + kc + b_kadd) * 2;
                ldsm4(bhf[p], bHiB + ro);
                ldsm4(blf[p], bLoB + ro);
            }
            #pragma unroll
            for (int i = 0; i < 2; ++i)
                #pragma unroll
                for (int jn = 0; jn < 4; ++jn) {
                    const int p = jn >> 1, q = (jn & 1) * 2;
                    mma16816(acc[i][jn], ah[i], bhf[p][q], bhf[p][q + 1]);
                    mma16816(acc[i][jn], ah[i], blf[p][q], blf[p][q + 1]);
                    mma16816(acc[i][jn], al[i], bhf[p][q], bhf[p][q + 1]);
                }
        }
    }

    // per-row z2 combine
    s_z2[ar][tid & 1] = z2a + z2b;
    __syncthreads();

    const int b = bh >> 4, h = bh & (HH - 1);
    const int g = lane >> 2, t = lane & 3;
    #pragma unroll
    for (int i = 0; i < 2; ++i) {
        #pragma unroll
        for (int half = 0; half < 2; ++half) {
            const int rl = wm * 32 + i * 16 + g + half * 8;
            const float inv = 1.0f / (s_z2[rl][0] + s_z2[rl][1]);
            const int q = q0 + rl;
            #pragma unroll
            for (int jn = 0; jn < 4; ++jn) {
                const int n = wn * 32 + jn * 8 + 2 * t;
                const float x0 = acc[i][jn][half * 2 + 0] * inv;
                const float x1 = acc[i][jn][half * 2 + 1] * inv;
                uint16_t h0, l0, h1, l1;
                split_bf(x0, h0, l0);
                split_bf(x1, h1, l1);
                const size_t base = (size_t)(b * SS + q) * DD + h * HD + n;
                *(uint32_t*)(g_valsH + base) = pack16(h0, h1);
                *(uint32_t*)(g_valsL + base) = pack16(l0, l1);
            }
        }
    }
}

// ===========================================================================
// Kernel 5: O projection — 256-thread CTAs (R11-proven), M=128 tile.
// ===========================================================================
__global__ __launch_bounds__(256) void oproj_mma_kernel(
    const float* __restrict__ ob, float* __restrict__ out)
{
    __shared__ __align__(16) __nv_bfloat16 sAh[128 * TSTRIDE];
    __shared__ __align__(16) __nv_bfloat16 sAl[128 * TSTRIDE];
    __shared__ __align__(16) __nv_bfloat16 sBh[64 * TSTRIDE];
    __shared__ __align__(16) __nv_bfloat16 sBl[64 * TSTRIDE];

    const int tid = threadIdx.x;
    const int lane = tid & 31, wid = tid >> 5;
    const int wm = wid & 3, wn = wid >> 2;
    const int m0 = blockIdx.x * 128;
    const int n0 = blockIdx.y * 64;

    const int ar = tid >> 1;
    const int ac = (tid & 1) * 16;
    const __nv_bfloat16* AhRow = g_valsH + (size_t)(m0 + ar) * DD + ac;
    const __nv_bfloat16* AlRow = g_valsL + (size_t)(m0 + ar) * DD + ac;
    const int vr = tid >> 2;
    const int vc = (tid & 3) * 8;
    const __nv_bfloat16* BhRow = g_OWh + (size_t)(n0 + vr) * DD + vc;
    const __nv_bfloat16* BlRow = g_OWl + (size_t)(n0 + vr) * DD + vc;

    const uint32_t ahB = smem_u32(sAh), alB = smem_u32(sAl);
    const uint32_t bhB = smem_u32(sBh), blB = smem_u32(sBl);
    const int a_row = wm * 32 + ((lane >> 3) & 1) * 8 + (lane & 7);
    const int a_kadd = ((lane >> 4) & 1) * 8;
    const int b_row = wn * 32 + ((lane >> 4) & 1) * 8 + (lane & 7);
    const int b_kadd = ((lane >> 3) & 1) * 8;

    float acc[2][4][4];
    #pragma unroll
    for (int i = 0; i < 2; i++)
        #pragma unroll
        for (int j = 0; j < 4; j++)
            #pragma unroll
            for (int r = 0; r < 4; r++) acc[i][j][r] = 0.f;

    uint4 a0h, a1h, a0l, a1l, b0h, b0l;
    a0h = *(const uint4*)(AhRow);      a1h = *(const uint4*)(AhRow + 8);
    a0l = *(const uint4*)(AlRow);      a1l = *(const uint4*)(AlRow + 8);
    b0h = *(const uint4*)(BhRow);      b0l = *(const uint4*)(BlRow);

    const int NCH = DD / 32;   // 32
    for (int c = 0; c < NCH; ++c) {
        __syncthreads();
        *(uint4*)(sAh + ar * TSTRIDE + ac)     = a0h;
        *(uint4*)(sAh + ar * TSTRIDE + ac + 8) = a1h;
        *(uint4*)(sAl + ar * TSTRIDE + ac)     = a0l;
        *(uint4*)(sAl + ar * TSTRIDE + ac + 8) = a1l;
        *(uint4*)(sBh + vr * TSTRIDE + vc) = b0h;
        *(uint4*)(sBl + vr * TSTRIDE + vc) = b0l;
        if (c + 1 < NCH) {
            a0h = *(const uint4*)(AhRow + (c + 1) * 32);
            a1h = *(const uint4*)(AhRow + (c + 1) * 32 + 8);
            a0l = *(const uint4*)(AlRow + (c + 1) * 32);
            a1l = *(const uint4*)(AlRow + (c + 1) * 32 + 8);
            b0h = *(const uint4*)(BhRow + (c + 1) * 32);
            b0l = *(const uint4*)(BlRow + (c + 1) * 32);
        }
        __syncthreads();

        #pragma unroll
        for (int ks = 0; ks < 2; ++ks) {
            const int kc = ks * 16;
            uint32_t fah[2][4], fal[2][4], fbh[2][4], fbl[2][4];
            #pragma unroll
            for (int i = 0; i < 2; ++i) {
                uint32_t ro = (uint32_t)((a_row + i * 16) * TSTRIDE + kc + a_kadd) * 2;
                ldsm4(fah[i], ahB + ro);
                ldsm4(fal[i], alB + ro);
            }
            #pragma unroll
            for (int p = 0; p < 2; ++p) {
                uint32_t ro = (uint32_t)((b_row + p * 16) * TSTRIDE + kc + b_kadd) * 2;
                ldsm4(fbh[p], bhB + ro);
                ldsm4(fbl[p], blB + ro);
            }
            #pragma unroll
            for (int i = 0; i < 2; ++i)
                #pragma unroll
                for (int jn = 0; jn < 4; ++jn) {
                    const int p = jn >> 1, q = (jn & 1) * 2;
                    mma16816(acc[i][jn], fah[i], fbh[p][q], fbh[p][q + 1]);
                    mma16816(acc[i][jn], fah[i], fbl[p][q], fbl[p][q + 1]);
                    mma16816(acc[i][jn], fal[i], fbh[p][q], fbh[p][q + 1]);
                }
        }
    }

    const int g = lane >> 2, t = lane & 3;
    #pragma unroll
    for (int i = 0; i < 2; ++i) {
        #pragma unroll
        for (int jn = 0; jn < 4; ++jn) {
            const int n = n0 + wn * 32 + jn * 8 + 2 * t;
            const float bx = ob[n], by = ob[n + 1];
            #pragma unroll
            for (int half = 0; half < 2; ++half) {
                const int m = m0 + wm * 32 + i * 16 + g + half * 8;
                float2 v;
                v.x = acc[i][jn][half * 2 + 0] + bx;
                v.y = acc[i][jn][half * 2 + 1] + by;
                *(float2*)(out + (size_t)m * DD + n) = v;
            }
        }
    }
}

// ===========================================================================
extern "C" void kernel_launch(void* const* d_in, const int* in_sizes, int n_in,
                              void* d_out, int out_size)
{
    const float *x = nullptr, *thr = nullptr, *qkvw = nullptr,
                *qkvb = nullptr, *ow = nullptr, *ob = nullptr;
    for (int i = 0; i < n_in; ++i) {
        const float* p = (const float*)d_in[i];
        switch (in_sizes[i]) {
            case MROWS * DD:   x = p;    break;
            case HH:           thr = p;  break;
            case E3D * DD:     qkvw = p; break;
            case E3D:          qkvb = p; break;
            case DD * DD:      ow = p;   break;
            case DD:           ob = p;   break;
        }
    }
    float* out = (float*)d_out;

    __half *Xh, *Xm, *Xl, *Wh, *Wm, *Wl;
    cudaGetSymbolAddress((void**)&Xh, g_Xh);
    cudaGetSymbolAddress((void**)&Xm, g_Xm);
    cudaGetSymbolAddress((void**)&Xl, g_Xl);
    cudaGetSymbolAddress((void**)&Wh, g_Wh);
    cudaGetSymbolAddress((void**)&Wm, g_Wm);
    cudaGetSymbolAddress((void**)&Wl, g_Wl);

    cudaFuncSetAttribute(qkv_mma_kernel, cudaFuncAttributeMaxDynamicSharedMemorySize, QKV_SMEM);
    cudaFuncSetAttribute(logits_mma_kernel, cudaFuncAttributeMaxDynamicSharedMemorySize, LG_SMEM);

    // launch index 3 (qkv) is the one ncu profiles — keep qkv there.
    split3_kernel<<<(MROWS * DD) / 1024, 256>>>(x, Xh, Xm, Xl);
    split3_kernel<<<(E3D * DD) / 1024, 256>>>(qkvw, Wh, Wm, Wl);
    owsplit_kernel<<<(DD * DD) / 1024, 256>>>(ow);
    qkv_mma_kernel<<<dim3(MROWS / 64, E3D / 64), 128, QKV_SMEM>>>(qkvb);
    vsplit_kernel<<<dim3(SS / 128, BH), 256>>>();
    logits_mma_kernel<<<dim3(SS / 64, SS / (64 * LG_NB), BH), 128, LG_SMEM>>>();
    combine_kernel<<<(BH * SS) / 8, 256>>>(thr);
    pv_mma_kernel<<<dim3(SS / 128, BH), 256>>>();
    oproj_mma_kernel<<<dim3(MROWS / 128, DD / 64), 256>>>(ob, out);
}